// round 7
// baseline (speedup 1.0000x reference)
#include <cuda_runtime.h>
#include <cuda_bf16.h>
#include <cstdint>

#define NN 4096
#define TT 8
#define KTOP 4
#define RR 8
#define DKK 64
#define BB 20

typedef unsigned long long ull;

__device__ __align__(16) float g_q[NN * DKK];
__device__ __align__(16) float g_k[NN * DKK];
__device__ __align__(16) float g_rq[NN * DKK];
__device__ __align__(16) __nv_bfloat16 g_qh[NN * DKK];
__device__ __align__(16) __nv_bfloat16 g_kh[NN * DKK];
__device__ __align__(16) float g_C[RR * 24 * 36];
__device__ __align__(16) int g_cand[NN * 256];
__device__ int g_ctx[NN * KTOP];
__device__ int g_rule[NN];

// ---------------- small helpers ----------------
__device__ __forceinline__ ull pack2(float a, float b) {
    ull r;
    asm("mov.b64 %0, {%1, %2};" : "=l"(r) : "f"(a), "f"(b));
    return r;
}
__device__ __forceinline__ void unpack2(ull v, float& a, float& b) {
    asm("mov.b64 {%0, %1}, %2;" : "=f"(a), "=f"(b) : "l"(v));
}
__device__ __forceinline__ ull fma2(ull a, ull b, ull c) {
    ull d;
    asm("fma.rn.f32x2 %0, %1, %2, %3;" : "=l"(d) : "l"(a), "l"(b), "l"(c));
    return d;
}
__device__ __forceinline__ void ins4(float v, int idx, float* tv, int* ti) {
    if (v > tv[3] || (v == tv[3] && idx < ti[3])) {
        tv[3] = v; ti[3] = idx;
#pragma unroll
        for (int j = 3; j > 0; j--) {
            bool sw = (tv[j] > tv[j - 1]) || (tv[j] == tv[j - 1] && ti[j] < ti[j - 1]);
            if (sw) {
                float f = tv[j]; tv[j] = tv[j - 1]; tv[j - 1] = f;
                int q = ti[j]; ti[j] = ti[j - 1]; ti[j - 1] = q;
            }
        }
    }
}
__device__ __forceinline__ uint32_t smem_to_u32(const void* p) {
    uint32_t a;
    asm("{ .reg .u64 t; cvta.to.shared.u64 t, %1; cvt.u32.u64 %0, t; }" : "=r"(a) : "l"(p));
    return a;
}
// XOR swizzle: rows of 128B, 16B chunks permuted by row
#define SWZ(row, byteoff) \
    ((row) * 128 + (((((byteoff) >> 4) ^ ((row) & 7)) << 4)) + ((byteoff) & 15))

// ---------------------------------------------------------------------------
// kA: x[4096x32] @ W[32x192] -> g_q | g_k | g_rq, plus bf16 copies of q,k
// 128 blocks x 256 thr; block = 32 rows; thread = 4 rows x 3 colpairs.
// ---------------------------------------------------------------------------
__global__ __launch_bounds__(256) void kA(
    const float* __restrict__ obs, const float* __restrict__ obs_vel,
    const float* __restrict__ wq_rule, const float* __restrict__ bq_rule,
    const float* __restrict__ wq_ctx, const float* __restrict__ bq_ctx,
    const float* __restrict__ wk_ctx, const float* __restrict__ bk_ctx)
{
    __shared__ __align__(16) ull x2_s[32 * 32];  // [kk][node], dup pairs
    __shared__ __align__(16) ull w_s[32 * 96];   // [kk][colpair]
    int tid = threadIdx.x;
    int n0 = blockIdx.x * 32;

    float* xf = (float*)x2_s;
    for (int e = tid; e < 32 * 32; e += 256) {
        int i = e >> 5, node = e & 31;
        int t = i >> 2, c = i & 3;
        const float* src = (c < 2) ? obs : obs_vel;
        float v = src[(c & 1) * NN * TT + (n0 + node) * TT + t];
        xf[e * 2] = v; xf[e * 2 + 1] = v;
    }
    float* wf = (float*)w_s;
    for (int e = tid; e < 32 * 192; e += 256) {
        int i = e / 192, col = e % 192;
        float v;
        if (col < 64) v = wq_ctx[i * 64 + col];
        else if (col < 128) v = wk_ctx[i * 64 + col - 64];
        else {
            int c = i & 3;
            if (c >= 2) v = wq_rule[((i >> 2) * 2 + (c - 2)) * 64 + (col - 128)];
            else v = 0.f;
        }
        wf[i * 192 + col] = v;
    }
    __syncthreads();

    int w = tid >> 5, tx = tid & 31;
    int rbase = w * 4;
    ull bp[3];
#pragma unroll
    for (int j = 0; j < 3; j++) {
        int c2 = (tx * 3 + j) * 2;
        float b0, b1;
        if (c2 < 64) { b0 = bq_ctx[c2]; b1 = bq_ctx[c2 + 1]; }
        else if (c2 < 128) { b0 = bk_ctx[c2 - 64]; b1 = bk_ctx[c2 - 63]; }
        else { b0 = bq_rule[c2 - 128]; b1 = bq_rule[c2 - 127]; }
        bp[j] = pack2(b0, b1);
    }
    ull acc[4][3];
#pragma unroll
    for (int r = 0; r < 4; r++)
#pragma unroll
        for (int j = 0; j < 3; j++) acc[r][j] = bp[j];

#pragma unroll 8
    for (int kk = 0; kk < 32; kk++) {
        const ulonglong2* qp = (const ulonglong2*)(x2_s + kk * 32 + rbase);
        ulonglong2 q0 = qp[0], q1 = qp[1];
        ull qr[4] = { q0.x, q0.y, q1.x, q1.y };
        ull wv0 = w_s[kk * 96 + tx * 3 + 0];
        ull wv1 = w_s[kk * 96 + tx * 3 + 1];
        ull wv2 = w_s[kk * 96 + tx * 3 + 2];
#pragma unroll
        for (int r = 0; r < 4; r++) {
            acc[r][0] = fma2(qr[r], wv0, acc[r][0]);
            acc[r][1] = fma2(qr[r], wv1, acc[r][1]);
            acc[r][2] = fma2(qr[r], wv2, acc[r][2]);
        }
    }
#pragma unroll
    for (int r = 0; r < 4; r++) {
        int node = n0 + rbase + r;
#pragma unroll
        for (int j = 0; j < 3; j++) {
            int c2 = (tx * 3 + j) * 2;
            float v0, v1;
            unpack2(acc[r][j], v0, v1);
            int cc = c2 & 63;
            if (c2 < 64) {
                g_q[node * 64 + cc] = v0;
                g_q[node * 64 + cc + 1] = v1;
                *(__nv_bfloat162*)&g_qh[node * 64 + cc] = __floats2bfloat162_rn(v0, v1);
            } else if (c2 < 128) {
                g_k[node * 64 + cc] = v0;
                g_k[node * 64 + cc + 1] = v1;
                *(__nv_bfloat162*)&g_kh[node * 64 + cc] = __floats2bfloat162_rn(v0, v1);
            } else {
                g_rq[node * 64 + cc] = v0;
                g_rq[node * 64 + cc + 1] = v1;
            }
        }
    }
}

// ---------------------------------------------------------------------------
// kR: rule argmax from g_rq @ rule_emb^T
// ---------------------------------------------------------------------------
__global__ __launch_bounds__(128) void kR(const float* __restrict__ rule_emb)
{
    __shared__ float s_emb[64 * 8];
    int tid = threadIdx.x;
    for (int e = tid; e < 512; e += 128) s_emb[e] = rule_emb[(e & 7) * 64 + (e >> 3)];
    __syncthreads();
    int n = blockIdx.x * 128 + tid;
    float lg[8];
#pragma unroll
    for (int r = 0; r < 8; r++) lg[r] = 0.f;
#pragma unroll
    for (int og = 0; og < 16; og++) {
        float4 v = *(const float4*)&g_rq[n * 64 + og * 4];
        float vv[4] = { v.x, v.y, v.z, v.w };
#pragma unroll
        for (int e = 0; e < 4; e++) {
            int o = og * 4 + e;
#pragma unroll
            for (int r = 0; r < 8; r++) lg[r] = fmaf(vv[e], s_emb[o * 8 + r], lg[r]);
        }
    }
    int best = 0;
    float bv = lg[0];
#pragma unroll
    for (int r = 1; r < 8; r++)
        if (lg[r] > bv) { bv = lg[r]; best = r; }
    g_rule[n] = best;
}

// ---------------------------------------------------------------------------
// kB_hmma: scores via mma.sync bf16 HMMA + per-thread top-4 candidates.
// grid (128 rowblocks, 4 colsplits) x 256 thr, 3 CTAs/SM -> 512 CTAs.
// CTA: 32 rows x 1024 cols, K=64; 4 tiles of 256 cols.
// smem: A 4KB + B 2x32KB (double-buffered cp.async) = 68KB dynamic.
// Candidates: 16 threads/row x top-4 x 4 splits = 256 per row -> g_cand.
// ---------------------------------------------------------------------------
__global__ __launch_bounds__(256, 3) void kB_hmma()
{
    extern __shared__ char smem[];
    char* As = smem;               // 32 x 128B
    char* Bs0 = smem + 4096;       // 256 x 128B
    char* Bs1 = smem + 4096 + 32768;
    int tid = threadIdx.x, lane = tid & 31, wid = tid >> 5;
    int row0 = blockIdx.x * 32;
    int split = blockIdx.y;
    int colbase = split * 1024;

    // stage A (swizzled): 32 rows x 8 chunks = 256
    {
        int r = tid >> 3, c = tid & 7;
        uint4 v = *(const uint4*)((const char*)g_qh + (size_t)(row0 + r) * 128 + c * 16);
        *(uint4*)(As + r * 128 + ((c ^ (r & 7)) << 4)) = v;
    }
    // prefetch B tile 0
    {
        int r = tid;
        const char* src = (const char*)g_kh + (size_t)(colbase + r) * 128;
        char* dst = Bs0 + r * 128;
#pragma unroll
        for (int c = 0; c < 8; c++) {
            uint32_t daddr = smem_to_u32(dst + ((c ^ (r & 7)) << 4));
            asm volatile("cp.async.cg.shared.global [%0], [%1], 16;"
                         :: "r"(daddr), "l"(src + c * 16));
        }
        asm volatile("cp.async.commit_group;");
    }
    __syncthreads();

    int rg = wid >> 2, ch = wid & 3;
    int m0 = rg * 16;

    // A fragments: a[k][0..3] for 4 k-steps of 16
    uint32_t a[4][4];
    {
        int arow = m0 + (lane & 15);
        int kbh = ((lane >> 4) & 1) * 16;
#pragma unroll
        for (int k = 0; k < 4; k++) {
            int byteoff = k * 32 + kbh;
            uint32_t addr = smem_to_u32(As + SWZ(arow, byteoff));
            asm volatile("ldmatrix.sync.aligned.m8n8.x4.shared.b16 {%0,%1,%2,%3}, [%4];"
                : "=r"(a[k][0]), "=r"(a[k][1]), "=r"(a[k][2]), "=r"(a[k][3]) : "r"(addr));
        }
    }

    int brow_off = (lane & 7) + ((lane & 16) >> 1);
    int bkb = (lane & 8) ? 16 : 0;

    float tv[2][4];
    int ti[2][4];
#pragma unroll
    for (int h = 0; h < 2; h++)
#pragma unroll
        for (int j = 0; j < 4; j++) { tv[h][j] = -3.4e38f; ti[h][j] = 0x7fffffff; }

    for (int t = 0; t < 4; t++) {
        if (t < 3) {
            char* dst0 = ((t + 1) & 1) ? Bs1 : Bs0;
            int r = tid;
            const char* src = (const char*)g_kh + (size_t)(colbase + (t + 1) * 256 + r) * 128;
            char* dst = dst0 + r * 128;
#pragma unroll
            for (int c = 0; c < 8; c++) {
                uint32_t daddr = smem_to_u32(dst + ((c ^ (r & 7)) << 4));
                asm volatile("cp.async.cg.shared.global [%0], [%1], 16;"
                             :: "r"(daddr), "l"(src + c * 16));
            }
            asm volatile("cp.async.commit_group;");
            asm volatile("cp.async.wait_group 1;");
        } else {
            asm volatile("cp.async.wait_group 0;");
        }
        __syncthreads();

        const char* B = (t & 1) ? Bs1 : Bs0;
        int coltile = colbase + t * 256;
#pragma unroll
        for (int np = 0; np < 4; np++) {
            int n0 = ch * 64 + np * 16;
            uint32_t b[4][4];
#pragma unroll
            for (int k = 0; k < 4; k++) {
                int brow = n0 + brow_off;
                int byteoff = k * 32 + bkb;
                uint32_t addr = smem_to_u32(B + SWZ(brow, byteoff));
                asm volatile("ldmatrix.sync.aligned.m8n8.x4.shared.b16 {%0,%1,%2,%3}, [%4];"
                    : "=r"(b[k][0]), "=r"(b[k][1]), "=r"(b[k][2]), "=r"(b[k][3]) : "r"(addr));
            }
            float c0[4] = {0.f, 0.f, 0.f, 0.f};
            float c1[4] = {0.f, 0.f, 0.f, 0.f};
#pragma unroll
            for (int k = 0; k < 4; k++) {
                asm volatile(
                    "mma.sync.aligned.m16n8k16.row.col.f32.bf16.bf16.f32 "
                    "{%0,%1,%2,%3}, {%4,%5,%6,%7}, {%8,%9}, {%0,%1,%2,%3};"
                    : "+f"(c0[0]), "+f"(c0[1]), "+f"(c0[2]), "+f"(c0[3])
                    : "r"(a[k][0]), "r"(a[k][1]), "r"(a[k][2]), "r"(a[k][3]),
                      "r"(b[k][0]), "r"(b[k][1]));
                asm volatile(
                    "mma.sync.aligned.m16n8k16.row.col.f32.bf16.bf16.f32 "
                    "{%0,%1,%2,%3}, {%4,%5,%6,%7}, {%8,%9}, {%0,%1,%2,%3};"
                    : "+f"(c1[0]), "+f"(c1[1]), "+f"(c1[2]), "+f"(c1[3])
                    : "r"(a[k][0]), "r"(a[k][1]), "r"(a[k][2]), "r"(a[k][3]),
                      "r"(b[k][2]), "r"(b[k][3]));
            }
            int colg = coltile + n0 + 2 * (lane & 3);
            float m0v = fmaxf(fmaxf(c0[0], c0[1]), fmaxf(c1[0], c1[1]));
            if (m0v >= tv[0][3]) {
                ins4(c0[0], colg, tv[0], ti[0]);
                ins4(c0[1], colg + 1, tv[0], ti[0]);
                ins4(c1[0], colg + 8, tv[0], ti[0]);
                ins4(c1[1], colg + 9, tv[0], ti[0]);
            }
            float m1v = fmaxf(fmaxf(c0[2], c0[3]), fmaxf(c1[2], c1[3]));
            if (m1v >= tv[1][3]) {
                ins4(c0[2], colg, tv[1], ti[1]);
                ins4(c0[3], colg + 1, tv[1], ti[1]);
                ins4(c1[2], colg + 8, tv[1], ti[1]);
                ins4(c1[3], colg + 9, tv[1], ti[1]);
            }
        }
        __syncthreads();
    }

    // write candidates: each row covered by 16 threads (4 ch-warps x 4 lanes)
    int slot = ch * 4 + (lane & 3);
    int rlo = row0 + m0 + (lane >> 2);
#pragma unroll
    for (int h = 0; h < 2; h++) {
        int row = rlo + h * 8;
        int base = row * 256 + split * 64 + slot * 4;
#pragma unroll
        for (int j = 0; j < 4; j++) g_cand[base + j] = ti[h][j];
    }
}

// ---------------------------------------------------------------------------
// kS: exact fp32 rescore of 256 candidates/row. Warp per row; 8 cands/lane,
// then parallel warp top-4 via sortable u64 keys (value desc, index asc).
// ---------------------------------------------------------------------------
__global__ __launch_bounds__(256) void kS()
{
    int tid = threadIdx.x, lane = tid & 31, wid = tid >> 5;
    int row = blockIdx.x * 8 + wid;

    float4 qv[16];
    const float4* qp = (const float4*)&g_q[row * 64];
#pragma unroll
    for (int i = 0; i < 16; i++) qv[i] = qp[i];

    int idxs[8];
    {
        const int4* cp = (const int4*)&g_cand[row * 256];
        int4 ca = cp[lane * 2], cb = cp[lane * 2 + 1];
        idxs[0] = ca.x; idxs[1] = ca.y; idxs[2] = ca.z; idxs[3] = ca.w;
        idxs[4] = cb.x; idxs[5] = cb.y; idxs[6] = cb.z; idxs[7] = cb.w;
    }
    ull key[8];
#pragma unroll
    for (int j = 0; j < 8; j++) {
        int idx = idxs[j];
        const float4* kp = (const float4*)&g_k[(size_t)idx * 64];
        float acc = 0.f;
#pragma unroll
        for (int i = 0; i < 16; i++) {
            float4 kv = kp[i];
            acc = fmaf(qv[i].x, kv.x, acc);
            acc = fmaf(qv[i].y, kv.y, acc);
            acc = fmaf(qv[i].z, kv.z, acc);
            acc = fmaf(qv[i].w, kv.w, acc);
        }
        uint32_t u = __float_as_uint(acc);
        u = (u & 0x80000000u) ? ~u : (u | 0x80000000u);
        key[j] = ((ull)u << 32) | (uint32_t)(~idx);
    }
#pragma unroll
    for (int r4 = 0; r4 < 4; r4++) {
        ull best = key[0];
#pragma unroll
        for (int j = 1; j < 8; j++) best = (key[j] > best) ? key[j] : best;
#pragma unroll
        for (int off = 16; off; off >>= 1) {
            ull o = __shfl_xor_sync(0xffffffff, best, off);
            if (o > best) best = o;
        }
        if (lane == 0) g_ctx[row * 4 + r4] = (int)(~(uint32_t)best);
#pragma unroll
        for (int j = 0; j < 8; j++)
            if (key[j] == best) key[j] = 0;
    }
}

// ---------------------------------------------------------------------------
// kP: precompute rule-combined time-conv matrices C[r][24][36]
// ---------------------------------------------------------------------------
__global__ void kP(
    const float* __restrict__ w_indiv, const float* __restrict__ w_social,
    const float* __restrict__ tp_w, const float* __restrict__ tp_b,
    const float* __restrict__ tpr_w, const float* __restrict__ tpr_b,
    const float* __restrict__ tpi_w, const float* __restrict__ tpi_b,
    const float* __restrict__ tpir_w, const float* __restrict__ tpir_b)
{
    int t = threadIdx.x;
    if (t >= 192) return;
    int r = t / 24, o2 = t % 24, o = o2 >> 1, pos = o2 & 1;
    float wi = w_indiv[r], ws = w_social[r];
    float* dst = g_C + (r * 24 + o2) * 36;
#pragma unroll
    for (int c = 0; c < 8; c++) {
        int wb = (r * 12 + o) * 8 + c;
        const float* wt = tpi_w + wb * 3;
        float wri = tpir_w[wb];
        float ci0 = pos == 0 ? (wt[1] + wri) : wt[0];
        float ci1 = pos == 0 ? wt[2] : (wt[1] + wri);
        dst[c] = wi * ci0;
        dst[8 + c] = wi * ci1;
        const float* ut = tp_w + wb * 3;
        float urs = tpr_w[wb];
        float cs0 = pos == 0 ? (ut[1] + urs) : ut[0];
        float cs1 = pos == 0 ? ut[2] : (ut[1] + urs);
        dst[16 + c] = ws * cs0;
        dst[24 + c] = ws * cs1;
    }
    dst[32] = wi * (tpi_b[r * 12 + o] + tpir_b[r * 12 + o])
            + ws * (tp_b[r * 12 + o] + tpr_b[r * 12 + o]);
    dst[33] = 0.f; dst[34] = 0.f; dst[35] = 0.f;
}

// ---------------------------------------------------------------------------
// kC: gather + selected-rule spatial convs + combined matvec. 8 nodes x 20 b.
// ---------------------------------------------------------------------------
__global__ __launch_bounds__(160) void kC(
    const float* __restrict__ obs_vel, const float* __restrict__ noise,
    const float* __restrict__ w_noise,
    const float* __restrict__ sp_w, const float* __restrict__ sp_b,
    const float* __restrict__ spr_w, const float* __restrict__ spr_b,
    const float* __restrict__ spi_w, const float* __restrict__ spi_b,
    const float* __restrict__ spir_w, const float* __restrict__ spir_b,
    float* __restrict__ out)
{
    __shared__ __align__(16) float s_C[8 * 24 * 36];
    __shared__ float s_sp_w[480], s_sp_b[16], s_spr_w[160], s_spr_b[16];
    __shared__ float s_spi_w[96], s_spi_b[16], s_spir_w[32], s_spir_b[16];
    __shared__ float s_wn[8], s_noise[BB * 2];
    __shared__ float s_ov[128], s_cvx[512];
    __shared__ int s_rule[8];

    int tid = threadIdx.x;
    int n0 = blockIdx.x * 8;

    for (int i = tid; i < 8 * 24 * 36; i += 160) s_C[i] = g_C[i];
    for (int i = tid; i < 480; i += 160) s_sp_w[i] = sp_w[i];
    if (tid < 160) s_spr_w[tid] = spr_w[tid];
    if (tid < 96) s_spi_w[tid] = spi_w[tid];
    if (tid < 32) s_spir_w[tid] = spir_w[tid];
    if (tid < 16) {
        s_sp_b[tid] = sp_b[tid]; s_spr_b[tid] = spr_b[tid];
        s_spi_b[tid] = spi_b[tid]; s_spir_b[tid] = spir_b[tid];
    }
    if (tid < 8) { s_wn[tid] = w_noise[tid]; s_rule[tid] = g_rule[n0 + tid]; }
    if (tid < 40) s_noise[tid] = noise[tid];
    for (int i = tid; i < 128; i += 160) {
        int node = i >> 4, s = (i >> 3) & 1, t = i & 7;
        s_ov[i] = obs_vel[s * NN * TT + (n0 + node) * TT + t];
    }
    for (int i = tid; i < 512; i += 160) {
        int node = i >> 6, rem = i & 63, k = rem >> 4, s = (rem >> 3) & 1, t = rem & 7;
        int nb = g_ctx[(n0 + node) * 4 + k];
        s_cvx[i] = obs_vel[s * NN * TT + nb * TT + t];
    }
    __syncthreads();

    int node = tid / 20, b = tid - node * 20;
    int n = n0 + node;
    int r = s_rule[node];
    float wn = s_wn[r];
    float nz0 = s_noise[b * 2 + 0] * wn;
    float nz1 = s_noise[b * 2 + 1] * wn;

    float v0[8], v1[8];
#pragma unroll
    for (int t = 0; t < 8; t++) {
        v0[t] = s_ov[node * 16 + t] + nz0;
        v1[t] = s_ov[node * 16 + 8 + t] + nz1;
    }

    float vals[32];

    {
        const float* pw3 = s_spi_w + r * 12;
        const float* pw1 = s_spir_w + r * 4;
#pragma unroll
        for (int so = 0; so < 2; so++) {
            float b3 = s_spi_b[r * 2 + so], b1 = s_spir_b[r * 2 + so];
            float w00 = pw3[so * 6 + 0], w01 = pw3[so * 6 + 1], w02 = pw3[so * 6 + 2];
            float w10 = pw3[so * 6 + 3], w11 = pw3[so * 6 + 4], w12 = pw3[so * 6 + 5];
            float wr0 = pw1[so * 2 + 0], wr1 = pw1[so * 2 + 1];
#pragma unroll
            for (int t = 0; t < 8; t++) {
                float a = b3;
                a = fmaf(w01, v0[t], a);
                a = fmaf(w11, v1[t], a);
                if (t > 0) { a = fmaf(w00, v0[t - 1], a); a = fmaf(w10, v1[t - 1], a); }
                if (t < 7) { a = fmaf(w02, v0[t + 1], a); a = fmaf(w12, v1[t + 1], a); }
                a = fmaxf(a, 0.f);
                float c1 = b1;
                c1 = fmaf(wr0, v0[t], c1);
                c1 = fmaf(wr1, v1[t], c1);
                vals[so * 8 + t] = a + c1;
            }
        }
    }

    {
        float a0[8], a1[8], c0[8], c1[8];
        float ba0 = s_sp_b[r * 2], ba1 = s_sp_b[r * 2 + 1];
        float bc0 = s_spr_b[r * 2], bc1 = s_spr_b[r * 2 + 1];
#pragma unroll
        for (int t = 0; t < 8; t++) { a0[t] = ba0; a1[t] = ba1; c0[t] = bc0; c1[t] = bc1; }
        const float* q3 = s_sp_w + r * 60;
        const float* q1 = s_spr_w + r * 20;

#define PROC_CH(ci, VV)                                                        \
        {                                                                      \
            float u0 = q3[(ci) * 3], u1 = q3[(ci) * 3 + 1], u2 = q3[(ci) * 3 + 2]; \
            float z0 = q3[30 + (ci) * 3], z1 = q3[30 + (ci) * 3 + 1], z2 = q3[30 + (ci) * 3 + 2]; \
            float ur = q1[(ci)], zr = q1[10 + (ci)];                           \
            _Pragma("unroll")                                                  \
            for (int t = 0; t < 8; t++) {                                      \
                float x = VV[t];                                               \
                a0[t] = fmaf(u1, x, a0[t]); a1[t] = fmaf(z1, x, a1[t]);        \
                c0[t] = fmaf(ur, x, c0[t]); c1[t] = fmaf(zr, x, c1[t]);        \
                if (t > 0) { a0[t] = fmaf(u0, VV[t - 1], a0[t]); a1[t] = fmaf(z0, VV[t - 1], a1[t]); } \
                if (t < 7) { a0[t] = fmaf(u2, VV[t + 1], a0[t]); a1[t] = fmaf(z2, VV[t + 1], a1[t]); } \
            }                                                                  \
        }

        PROC_CH(0, v0)
        PROC_CH(1, v1)
#pragma unroll
        for (int k = 0; k < 4; k++) {
            float nb0[8], nb1[8];
#pragma unroll
            for (int t = 0; t < 8; t++) {
                nb0[t] = s_cvx[node * 64 + k * 16 + t] + nz0;
                nb1[t] = s_cvx[node * 64 + k * 16 + 8 + t] + nz1;
            }
            PROC_CH(2 + k * 2 + 0, nb0)
            PROC_CH(2 + k * 2 + 1, nb1)
        }
#undef PROC_CH
#pragma unroll
        for (int t = 0; t < 8; t++) {
            vals[16 + t] = fmaxf(a0[t], 0.f) + c0[t];
            vals[24 + t] = fmaxf(a1[t], 0.f) + c1[t];
        }
    }

    ull pk[16];
#pragma unroll
    for (int p = 0; p < 16; p++) pk[p] = pack2(vals[2 * p], vals[2 * p + 1]);

    const float* Cb = s_C + r * 24 * 36;
    float* outp = out + ((size_t)b * NN + n) * 24;
#pragma unroll 4
    for (int o2 = 0; o2 < 24; o2++) {
        const ulonglong2* cp = (const ulonglong2*)(Cb + o2 * 36);
        ull acc = pack2(Cb[o2 * 36 + 32], 0.f);
#pragma unroll
        for (int p = 0; p < 8; p++) {
            ulonglong2 cc = cp[p];
            acc = fma2(cc.x, pk[2 * p], acc);
            acc = fma2(cc.y, pk[2 * p + 1], acc);
        }
        float lo, hi;
        unpack2(acc, lo, hi);
        outp[o2] = lo + hi;
    }
}

// ---------------------------------------------------------------------------
extern "C" void kernel_launch(void* const* d_in, const int* in_sizes, int n_in,
                              void* d_out, int out_size)
{
    const float* obs      = (const float*)d_in[0];
    const float* obs_vel  = (const float*)d_in[1];
    const float* noise    = (const float*)d_in[2];
    const float* wq_rule  = (const float*)d_in[3];
    const float* bq_rule  = (const float*)d_in[4];
    const float* wq_ctx   = (const float*)d_in[5];
    const float* bq_ctx   = (const float*)d_in[6];
    const float* wk_ctx   = (const float*)d_in[7];
    const float* bk_ctx   = (const float*)d_in[8];
    const float* rule_emb = (const float*)d_in[9];
    const float* w_noise  = (const float*)d_in[10];
    const float* w_indiv  = (const float*)d_in[11];
    const float* w_social = (const float*)d_in[12];
    const float* sp_w  = (const float*)d_in[13];
    const float* sp_b  = (const float*)d_in[14];
    const float* spr_w = (const float*)d_in[15];
    const float* spr_b = (const float*)d_in[16];
    const float* tp_w  = (const float*)d_in[17];
    const float* tp_b  = (const float*)d_in[18];
    const float* tpr_w = (const float*)d_in[19];
    const float* tpr_b = (const float*)d_in[20];
    const float* spi_w  = (const float*)d_in[21];
    const float* spi_b  = (const float*)d_in[22];
    const float* spir_w = (const float*)d_in[23];
    const float* spir_b = (const float*)d_in[24];
    const float* tpi_w  = (const float*)d_in[25];
    const float* tpi_b  = (const float*)d_in[26];
    const float* tpir_w = (const float*)d_in[27];
    const float* tpir_b = (const float*)d_in[28];
    float* out = (float*)d_out;

    static bool attr_set = false;
    if (!attr_set) {
        cudaFuncSetAttribute(kB_hmma, cudaFuncAttributeMaxDynamicSharedMemorySize, 69632);
        attr_set = true;
    }

    kA<<<128, 256>>>(obs, obs_vel, wq_rule, bq_rule, wq_ctx, bq_ctx, wk_ctx, bk_ctx);
    kR<<<32, 128>>>(rule_emb);
    kP<<<1, 192>>>(w_indiv, w_social, tp_w, tp_b, tpr_w, tpr_b,
                   tpi_w, tpi_b, tpir_w, tpir_b);
    kB_hmma<<<dim3(128, 4), 256, 69632>>>();
    kS<<<512, 256>>>();
    kC<<<512, 160>>>(obs_vel, noise, w_noise,
                     sp_w, sp_b, spr_w, spr_b,
                     spi_w, spi_b, spir_w, spir_b, out);
}

// round 9
// speedup vs baseline: 1.2787x; 1.2787x over previous
#include <cuda_runtime.h>
#include <cuda_bf16.h>
#include <cstdint>

#define NN 4096
#define TT 8
#define KTOP 4
#define RR 8
#define DKK 64
#define BB 20

typedef unsigned long long ull;

__device__ __align__(16) float g_q[NN * DKK];
__device__ __align__(16) float g_k[NN * DKK];
__device__ __align__(16) float g_rq[NN * DKK];
__device__ __align__(16) __nv_bfloat16 g_qh[NN * DKK];
__device__ __align__(16) __nv_bfloat16 g_kh[NN * DKK];
__device__ __align__(16) float g_C[RR * 24 * 36];
__device__ __align__(16) int g_cand[NN * 128];
__device__ int g_ctx[NN * KTOP];
__device__ int g_rule[NN];

// ---------------- small helpers ----------------
__device__ __forceinline__ ull pack2(float a, float b) {
    ull r;
    asm("mov.b64 %0, {%1, %2};" : "=l"(r) : "f"(a), "f"(b));
    return r;
}
__device__ __forceinline__ void unpack2(ull v, float& a, float& b) {
    asm("mov.b64 {%0, %1}, %2;" : "=f"(a), "=f"(b) : "l"(v));
}
__device__ __forceinline__ ull fma2(ull a, ull b, ull c) {
    ull d;
    asm("fma.rn.f32x2 %0, %1, %2, %3;" : "=l"(d) : "l"(a), "l"(b), "l"(c));
    return d;
}
// unordered keep-4-largest (candidate pool; exact ranking done later in kS)
__device__ __forceinline__ void insU(float v, int c, float* tv, int* ti, float& vmin) {
    if (v > vmin) {
        bool done = false;
#pragma unroll
        for (int j = 0; j < 4; j++) {
            if (!done && tv[j] == vmin) { tv[j] = v; ti[j] = c; done = true; }
        }
        vmin = fminf(fminf(tv[0], tv[1]), fminf(tv[2], tv[3]));
    }
}
__device__ __forceinline__ uint32_t smem_to_u32(const void* p) {
    uint32_t a;
    asm("{ .reg .u64 t; cvta.to.shared.u64 t, %1; cvt.u32.u64 %0, t; }" : "=r"(a) : "l"(p));
    return a;
}
#define SWZ(row, byteoff) \
    ((row) * 128 + (((((byteoff) >> 4) ^ ((row) & 7)) << 4)) + ((byteoff) & 15))

// ---------------------------------------------------------------------------
// kA: x[4096x32] @ W[32x192] -> g_q | g_k | g_rq, plus bf16 copies of q,k
// ---------------------------------------------------------------------------
__global__ __launch_bounds__(256) void kA(
    const float* __restrict__ obs, const float* __restrict__ obs_vel,
    const float* __restrict__ wq_rule, const float* __restrict__ bq_rule,
    const float* __restrict__ wq_ctx, const float* __restrict__ bq_ctx,
    const float* __restrict__ wk_ctx, const float* __restrict__ bk_ctx)
{
    __shared__ __align__(16) ull x2_s[32 * 64];
    __shared__ __align__(16) ull w_s[32 * 96];
    int tid = threadIdx.x;
    int n0 = blockIdx.x * 64;

    float* xf = (float*)x2_s;
    for (int e = tid; e < 32 * 64; e += 256) {
        int i = e >> 6, node = e & 63;
        int t = i >> 2, c = i & 3;
        const float* src = (c < 2) ? obs : obs_vel;
        float v = src[(c & 1) * NN * TT + (n0 + node) * TT + t];
        xf[e * 2] = v; xf[e * 2 + 1] = v;
    }
    float* wf = (float*)w_s;
    for (int e = tid; e < 32 * 192; e += 256) {
        int i = e / 192, col = e % 192;
        float v;
        if (col < 64) v = wq_ctx[i * 64 + col];
        else if (col < 128) v = wk_ctx[i * 64 + col - 64];
        else {
            int c = i & 3;
            if (c >= 2) v = wq_rule[((i >> 2) * 2 + (c - 2)) * 64 + (col - 128)];
            else v = 0.f;
        }
        wf[i * 192 + col] = v;
    }
    __syncthreads();

    int w = tid >> 5, tx = tid & 31;
    int rbase = w * 8;
    ull bp[3];
#pragma unroll
    for (int j = 0; j < 3; j++) {
        int c2 = (tx * 3 + j) * 2;
        float b0, b1;
        if (c2 < 64) { b0 = bq_ctx[c2]; b1 = bq_ctx[c2 + 1]; }
        else if (c2 < 128) { b0 = bk_ctx[c2 - 64]; b1 = bk_ctx[c2 - 63]; }
        else { b0 = bq_rule[c2 - 128]; b1 = bq_rule[c2 - 127]; }
        bp[j] = pack2(b0, b1);
    }
    ull acc[8][3];
#pragma unroll
    for (int r = 0; r < 8; r++)
#pragma unroll
        for (int j = 0; j < 3; j++) acc[r][j] = bp[j];

#pragma unroll 8
    for (int kk = 0; kk < 32; kk++) {
        const ulonglong2* qp = (const ulonglong2*)(x2_s + kk * 64 + rbase);
        ulonglong2 q0 = qp[0], q1 = qp[1], q2v = qp[2], q3 = qp[3];
        ull qr[8] = { q0.x, q0.y, q1.x, q1.y, q2v.x, q2v.y, q3.x, q3.y };
        ull wv0 = w_s[kk * 96 + tx * 3 + 0];
        ull wv1 = w_s[kk * 96 + tx * 3 + 1];
        ull wv2 = w_s[kk * 96 + tx * 3 + 2];
#pragma unroll
        for (int r = 0; r < 8; r++) {
            acc[r][0] = fma2(qr[r], wv0, acc[r][0]);
            acc[r][1] = fma2(qr[r], wv1, acc[r][1]);
            acc[r][2] = fma2(qr[r], wv2, acc[r][2]);
        }
    }
#pragma unroll
    for (int r = 0; r < 8; r++) {
        int node = n0 + rbase + r;
#pragma unroll
        for (int j = 0; j < 3; j++) {
            int c2 = (tx * 3 + j) * 2;
            float v0, v1;
            unpack2(acc[r][j], v0, v1);
            int cc = c2 & 63;
            if (c2 < 64) {
                g_q[node * 64 + cc] = v0;
                g_q[node * 64 + cc + 1] = v1;
                *(__nv_bfloat162*)&g_qh[node * 64 + cc] = __floats2bfloat162_rn(v0, v1);
            } else if (c2 < 128) {
                g_k[node * 64 + cc] = v0;
                g_k[node * 64 + cc + 1] = v1;
                *(__nv_bfloat162*)&g_kh[node * 64 + cc] = __floats2bfloat162_rn(v0, v1);
            } else {
                g_rq[node * 64 + cc] = v0;
                g_rq[node * 64 + cc + 1] = v1;
            }
        }
    }
}

// ---------------------------------------------------------------------------
// kR: rule argmax from g_rq @ rule_emb^T
// ---------------------------------------------------------------------------
__global__ __launch_bounds__(128) void kR(const float* __restrict__ rule_emb)
{
    __shared__ float s_emb[64 * 8];
    int tid = threadIdx.x;
    for (int e = tid; e < 512; e += 128) s_emb[e] = rule_emb[(e & 7) * 64 + (e >> 3)];
    __syncthreads();
    int n = blockIdx.x * 128 + tid;
    float lg[8];
#pragma unroll
    for (int r = 0; r < 8; r++) lg[r] = 0.f;
#pragma unroll
    for (int og = 0; og < 16; og++) {
        float4 v = *(const float4*)&g_rq[n * 64 + og * 4];
        float vv[4] = { v.x, v.y, v.z, v.w };
#pragma unroll
        for (int e = 0; e < 4; e++) {
            int o = og * 4 + e;
#pragma unroll
            for (int r = 0; r < 8; r++) lg[r] = fmaf(vv[e], s_emb[o * 8 + r], lg[r]);
        }
    }
    int best = 0;
    float bv = lg[0];
#pragma unroll
    for (int r = 1; r < 8; r++)
        if (lg[r] > bv) { bv = lg[r]; best = r; }
    g_rule[n] = best;
}

// ---------------------------------------------------------------------------
// kB_hmma: scores via mma.sync bf16 HMMA + per-thread keep-4 candidates.
// grid (128 rowblocks, 2 colsplits) x 256 thr, 3 CTAs/SM cap.
// CTA: 32 rows x 2048 cols, K=64; 8 tiles of 256 cols.
// smem: A 4KB + B 2x32KB (double-buffered cp.async) = 68KB dynamic.
// Candidates: 16 threads/row x 4 x 2 splits = 128 per row -> g_cand.
// ---------------------------------------------------------------------------
__global__ __launch_bounds__(256, 3) void kB_hmma()
{
    extern __shared__ char smem[];
    char* As = smem;               // 32 x 128B
    char* Bs0 = smem + 4096;       // 256 x 128B
    char* Bs1 = smem + 4096 + 32768;
    int tid = threadIdx.x, lane = tid & 31, wid = tid >> 5;
    int row0 = blockIdx.x * 32;
    int split = blockIdx.y;
    int colbase = split * 2048;

    // stage A (swizzled): 32 rows x 8 chunks = 256
    {
        int r = tid >> 3, c = tid & 7;
        uint4 v = *(const uint4*)((const char*)g_qh + (size_t)(row0 + r) * 128 + c * 16);
        *(uint4*)(As + r * 128 + ((c ^ (r & 7)) << 4)) = v;
    }
    // prefetch B tile 0
    {
        int r = tid;
        const char* src = (const char*)g_kh + (size_t)(colbase + r) * 128;
        char* dst = Bs0 + r * 128;
#pragma unroll
        for (int c = 0; c < 8; c++) {
            uint32_t daddr = smem_to_u32(dst + ((c ^ (r & 7)) << 4));
            asm volatile("cp.async.cg.shared.global [%0], [%1], 16;"
                         :: "r"(daddr), "l"(src + c * 16));
        }
        asm volatile("cp.async.commit_group;");
    }
    __syncthreads();

    int rg = wid >> 2, ch = wid & 3;
    int m0 = rg * 16;

    uint32_t a[4][4];
    {
        int arow = m0 + (lane & 15);
        int kbh = ((lane >> 4) & 1) * 16;
#pragma unroll
        for (int k = 0; k < 4; k++) {
            int byteoff = k * 32 + kbh;
            uint32_t addr = smem_to_u32(As + SWZ(arow, byteoff));
            asm volatile("ldmatrix.sync.aligned.m8n8.x4.shared.b16 {%0,%1,%2,%3}, [%4];"
                : "=r"(a[k][0]), "=r"(a[k][1]), "=r"(a[k][2]), "=r"(a[k][3]) : "r"(addr));
        }
    }

    int brow_off = (lane & 7) + ((lane & 16) >> 1);
    int bkb = (lane & 8) ? 16 : 0;

    float tv[2][4];
    int ti[2][4];
    float vmin0 = -3.4e38f, vmin1 = -3.4e38f;
#pragma unroll
    for (int h = 0; h < 2; h++)
#pragma unroll
        for (int j = 0; j < 4; j++) { tv[h][j] = -3.4e38f; ti[h][j] = 0; }

    for (int t = 0; t < 8; t++) {
        if (t < 7) {
            char* dst0 = ((t + 1) & 1) ? Bs1 : Bs0;
            int r = tid;
            const char* src = (const char*)g_kh + (size_t)(colbase + (t + 1) * 256 + r) * 128;
            char* dst = dst0 + r * 128;
#pragma unroll
            for (int c = 0; c < 8; c++) {
                uint32_t daddr = smem_to_u32(dst + ((c ^ (r & 7)) << 4));
                asm volatile("cp.async.cg.shared.global [%0], [%1], 16;"
                             :: "r"(daddr), "l"(src + c * 16));
            }
            asm volatile("cp.async.commit_group;");
            asm volatile("cp.async.wait_group 1;");
        } else {
            asm volatile("cp.async.wait_group 0;");
        }
        __syncthreads();

        const char* B = (t & 1) ? Bs1 : Bs0;
        int coltile = colbase + t * 256;
#pragma unroll
        for (int np = 0; np < 4; np++) {
            int n0 = ch * 64 + np * 16;
            uint32_t b[4][4];
#pragma unroll
            for (int k = 0; k < 4; k++) {
                int brow = n0 + brow_off;
                int byteoff = k * 32 + bkb;
                uint32_t addr = smem_to_u32(B + SWZ(brow, byteoff));
                asm volatile("ldmatrix.sync.aligned.m8n8.x4.shared.b16 {%0,%1,%2,%3}, [%4];"
                    : "=r"(b[k][0]), "=r"(b[k][1]), "=r"(b[k][2]), "=r"(b[k][3]) : "r"(addr));
            }
            float c0[4] = {0.f, 0.f, 0.f, 0.f};
            float c1[4] = {0.f, 0.f, 0.f, 0.f};
#pragma unroll
            for (int k = 0; k < 4; k++) {
                asm volatile(
                    "mma.sync.aligned.m16n8k16.row.col.f32.bf16.bf16.f32 "
                    "{%0,%1,%2,%3}, {%4,%5,%6,%7}, {%8,%9}, {%0,%1,%2,%3};"
                    : "+f"(c0[0]), "+f"(c0[1]), "+f"(c0[2]), "+f"(c0[3])
                    : "r"(a[k][0]), "r"(a[k][1]), "r"(a[k][2]), "r"(a[k][3]),
                      "r"(b[k][0]), "r"(b[k][1]));
                asm volatile(
                    "mma.sync.aligned.m16n8k16.row.col.f32.bf16.bf16.f32 "
                    "{%0,%1,%2,%3}, {%4,%5,%6,%7}, {%8,%9}, {%0,%1,%2,%3};"
                    : "+f"(c1[0]), "+f"(c1[1]), "+f"(c1[2]), "+f"(c1[3])
                    : "r"(a[k][0]), "r"(a[k][1]), "r"(a[k][2]), "r"(a[k][3]),
                      "r"(b[k][2]), "r"(b[k][3]));
            }
            int colg = coltile + n0 + 2 * (lane & 3);
            // row-half 0: c0[0],c0[1],c1[0],c1[1]
            float m0v = fmaxf(fmaxf(c0[0], c0[1]), fmaxf(c1[0], c1[1]));
            if (m0v > vmin0) {
                insU(c0[0], colg, tv[0], ti[0], vmin0);
                insU(c0[1], colg + 1, tv[0], ti[0], vmin0);
                insU(c1[0], colg + 8, tv[0], ti[0], vmin0);
                insU(c1[1], colg + 9, tv[0], ti[0], vmin0);
            }
            // row-half 1: c0[2],c0[3],c1[2],c1[3]
            float m1v = fmaxf(fmaxf(c0[2], c0[3]), fmaxf(c1[2], c1[3]));
            if (m1v > vmin1) {
                insU(c0[2], colg, tv[1], ti[1], vmin1);
                insU(c0[3], colg + 1, tv[1], ti[1], vmin1);
                insU(c1[2], colg + 8, tv[1], ti[1], vmin1);
                insU(c1[3], colg + 9, tv[1], ti[1], vmin1);
            }
        }
        __syncthreads();
    }

    // write candidates: each row covered by 16 threads (4 ch-warps x 4 lanes)
    int slot = ch * 4 + (lane & 3);
    int rlo = row0 + m0 + (lane >> 2);
#pragma unroll
    for (int h = 0; h < 2; h++) {
        int row = rlo + h * 8;
        int base = row * 128 + split * 64 + slot * 4;
#pragma unroll
        for (int j = 0; j < 4; j++) g_cand[base + j] = ti[h][j];
    }
}

// ---------------------------------------------------------------------------
// kS: exact fp32 rescore of 128 candidates/row. Warp per row; 4 cands/lane,
// parallel warp top-4 via sortable u64 keys (value desc, index asc).
// ---------------------------------------------------------------------------
__global__ __launch_bounds__(256) void kS()
{
    int tid = threadIdx.x, lane = tid & 31, wid = tid >> 5;
    int row = blockIdx.x * 8 + wid;

    float4 qv[16];
    const float4* qp = (const float4*)&g_q[row * 64];
#pragma unroll
    for (int i = 0; i < 16; i++) qv[i] = qp[i];

    int idxs[4];
    {
        int4 ca = ((const int4*)&g_cand[row * 128])[lane];
        idxs[0] = ca.x; idxs[1] = ca.y; idxs[2] = ca.z; idxs[3] = ca.w;
    }
    ull key[4];
#pragma unroll
    for (int j = 0; j < 4; j++) {
        int idx = idxs[j];
        const float4* kp = (const float4*)&g_k[(size_t)idx * 64];
        float acc = 0.f;
#pragma unroll
        for (int i = 0; i < 16; i++) {
            float4 kv = kp[i];
            acc = fmaf(qv[i].x, kv.x, acc);
            acc = fmaf(qv[i].y, kv.y, acc);
            acc = fmaf(qv[i].z, kv.z, acc);
            acc = fmaf(qv[i].w, kv.w, acc);
        }
        uint32_t u = __float_as_uint(acc);
        u = (u & 0x80000000u) ? ~u : (u | 0x80000000u);
        key[j] = ((ull)u << 32) | (uint32_t)(~idx);
    }
#pragma unroll
    for (int r4 = 0; r4 < 4; r4++) {
        ull best = key[0];
#pragma unroll
        for (int j = 1; j < 4; j++) best = (key[j] > best) ? key[j] : best;
#pragma unroll
        for (int off = 16; off; off >>= 1) {
            ull o = __shfl_xor_sync(0xffffffff, best, off);
            if (o > best) best = o;
        }
        if (lane == 0) g_ctx[row * 4 + r4] = (int)(~(uint32_t)best);
#pragma unroll
        for (int j = 0; j < 4; j++)
            if (key[j] == best) key[j] = 0;
    }
}

// ---------------------------------------------------------------------------
// kP: precompute rule-combined time-conv matrices C[r][24][36]
// ---------------------------------------------------------------------------
__global__ void kP(
    const float* __restrict__ w_indiv, const float* __restrict__ w_social,
    const float* __restrict__ tp_w, const float* __restrict__ tp_b,
    const float* __restrict__ tpr_w, const float* __restrict__ tpr_b,
    const float* __restrict__ tpi_w, const float* __restrict__ tpi_b,
    const float* __restrict__ tpir_w, const float* __restrict__ tpir_b)
{
    int t = threadIdx.x;
    if (t >= 192) return;
    int r = t / 24, o2 = t % 24, o = o2 >> 1, pos = o2 & 1;
    float wi = w_indiv[r], ws = w_social[r];
    float* dst = g_C + (r * 24 + o2) * 36;
#pragma unroll
    for (int c = 0; c < 8; c++) {
        int wb = (r * 12 + o) * 8 + c;
        const float* wt = tpi_w + wb * 3;
        float wri = tpir_w[wb];
        float ci0 = pos == 0 ? (wt[1] + wri) : wt[0];
        float ci1 = pos == 0 ? wt[2] : (wt[1] + wri);
        dst[c] = wi * ci0;
        dst[8 + c] = wi * ci1;
        const float* ut = tp_w + wb * 3;
        float urs = tpr_w[wb];
        float cs0 = pos == 0 ? (ut[1] + urs) : ut[0];
        float cs1 = pos == 0 ? ut[2] : (ut[1] + urs);
        dst[16 + c] = ws * cs0;
        dst[24 + c] = ws * cs1;
    }
    dst[32] = wi * (tpi_b[r * 12 + o] + tpir_b[r * 12 + o])
            + ws * (tp_b[r * 12 + o] + tpr_b[r * 12 + o]);
    dst[33] = 0.f; dst[34] = 0.f; dst[35] = 0.f;
}

// ---------------------------------------------------------------------------
// kC: gather + selected-rule spatial convs + combined matvec. 8 nodes x 20 b.
// ---------------------------------------------------------------------------
__global__ __launch_bounds__(160) void kC(
    const float* __restrict__ obs_vel, const float* __restrict__ noise,
    const float* __restrict__ w_noise,
    const float* __restrict__ sp_w, const float* __restrict__ sp_b,
    const float* __restrict__ spr_w, const float* __restrict__ spr_b,
    const float* __restrict__ spi_w, const float* __restrict__ spi_b,
    const float* __restrict__ spir_w, const float* __restrict__ spir_b,
    float* __restrict__ out)
{
    __shared__ __align__(16) float s_C[8 * 24 * 36];
    __shared__ float s_sp_w[480], s_sp_b[16], s_spr_w[160], s_spr_b[16];
    __shared__ float s_spi_w[96], s_spi_b[16], s_spir_w[32], s_spir_b[16];
    __shared__ float s_wn[8], s_noise[BB * 2];
    __shared__ float s_ov[128], s_cvx[512];
    __shared__ int s_rule[8];

    int tid = threadIdx.x;
    int n0 = blockIdx.x * 8;

    for (int i = tid; i < 8 * 24 * 36; i += 160) s_C[i] = g_C[i];
    for (int i = tid; i < 480; i += 160) s_sp_w[i] = sp_w[i];
    if (tid < 160) s_spr_w[tid] = spr_w[tid];
    if (tid < 96) s_spi_w[tid] = spi_w[tid];
    if (tid < 32) s_spir_w[tid] = spir_w[tid];
    if (tid < 16) {
        s_sp_b[tid] = sp_b[tid]; s_spr_b[tid] = spr_b[tid];
        s_spi_b[tid] = spi_b[tid]; s_spir_b[tid] = spir_b[tid];
    }
    if (tid < 8) { s_wn[tid] = w_noise[tid]; s_rule[tid] = g_rule[n0 + tid]; }
    if (tid < 40) s_noise[tid] = noise[tid];
    for (int i = tid; i < 128; i += 160) {
        int node = i >> 4, s = (i >> 3) & 1, t = i & 7;
        s_ov[i] = obs_vel[s * NN * TT + (n0 + node) * TT + t];
    }
    for (int i = tid; i < 512; i += 160) {
        int node = i >> 6, rem = i & 63, k = rem >> 4, s = (rem >> 3) & 1, t = rem & 7;
        int nb = g_ctx[(n0 + node) * 4 + k];
        s_cvx[i] = obs_vel[s * NN * TT + nb * TT + t];
    }
    __syncthreads();

    int node = tid / 20, b = tid - node * 20;
    int n = n0 + node;
    int r = s_rule[node];
    float wn = s_wn[r];
    float nz0 = s_noise[b * 2 + 0] * wn;
    float nz1 = s_noise[b * 2 + 1] * wn;

    float v0[8], v1[8];
#pragma unroll
    for (int t = 0; t < 8; t++) {
        v0[t] = s_ov[node * 16 + t] + nz0;
        v1[t] = s_ov[node * 16 + 8 + t] + nz1;
    }

    float vals[32];

    {
        const float* pw3 = s_spi_w + r * 12;
        const float* pw1 = s_spir_w + r * 4;
#pragma unroll
    for (int so = 0; so < 2; so++) {
            float b3 = s_spi_b[r * 2 + so], b1 = s_spir_b[r * 2 + so];
            float w00 = pw3[so * 6 + 0], w01 = pw3[so * 6 + 1], w02 = pw3[so * 6 + 2];
            float w10 = pw3[so * 6 + 3], w11 = pw3[so * 6 + 4], w12 = pw3[so * 6 + 5];
            float wr0 = pw1[so * 2 + 0], wr1 = pw1[so * 2 + 1];
#pragma unroll
            for (int t = 0; t < 8; t++) {
                float a = b3;
                a = fmaf(w01, v0[t], a);
                a = fmaf(w11, v1[t], a);
                if (t > 0) { a = fmaf(w00, v0[t - 1], a); a = fmaf(w10, v1[t - 1], a); }
                if (t < 7) { a = fmaf(w02, v0[t + 1], a); a = fmaf(w12, v1[t + 1], a); }
                a = fmaxf(a, 0.f);
                float c1 = b1;
                c1 = fmaf(wr0, v0[t], c1);
                c1 = fmaf(wr1, v1[t], c1);
                vals[so * 8 + t] = a + c1;
            }
        }
    }

    {
        float a0[8], a1[8], c0[8], c1[8];
        float ba0 = s_sp_b[r * 2], ba1 = s_sp_b[r * 2 + 1];
        float bc0 = s_spr_b[r * 2], bc1 = s_spr_b[r * 2 + 1];
#pragma unroll
        for (int t = 0; t < 8; t++) { a0[t] = ba0; a1[t] = ba1; c0[t] = bc0; c1[t] = bc1; }
        const float* q3 = s_sp_w + r * 60;
        const float* q1 = s_spr_w + r * 20;

#define PROC_CH(ci, VV)                                                        \
        {                                                                      \
            float u0 = q3[(ci) * 3], u1 = q3[(ci) * 3 + 1], u2 = q3[(ci) * 3 + 2]; \
            float z0 = q3[30 + (ci) * 3], z1 = q3[30 + (ci) * 3 + 1], z2 = q3[30 + (ci) * 3 + 2]; \
            float ur = q1[(ci)], zr = q1[10 + (ci)];                           \
            _Pragma("unroll")                                                  \
            for (int t = 0; t < 8; t++) {                                      \
                float x = VV[t];                                               \
                a0[t] = fmaf(u1, x, a0[t]); a1[t] = fmaf(z1, x, a1[t]);        \
                c0[t] = fmaf(ur, x, c0[t]); c1[t] = fmaf(zr, x, c1[t]);        \
                if (t > 0) { a0[t] = fmaf(u0, VV[t - 1], a0[t]); a1[t] = fmaf(z0, VV[t - 1], a1[t]); } \
                if (t < 7) { a0[t] = fmaf(u2, VV[t + 1], a0[t]); a1[t] = fmaf(z2, VV[t + 1], a1[t]); } \
            }                                                                  \
        }

        PROC_CH(0, v0)
        PROC_CH(1, v1)
#pragma unroll
        for (int k = 0; k < 4; k++) {
            float nb0[8], nb1[8];
#pragma unroll
            for (int t = 0; t < 8; t++) {
                nb0[t] = s_cvx[node * 64 + k * 16 + t] + nz0;
                nb1[t] = s_cvx[node * 64 + k * 16 + 8 + t] + nz1;
            }
            PROC_CH(2 + k * 2 + 0, nb0)
            PROC_CH(2 + k * 2 + 1, nb1)
        }
#undef PROC_CH
#pragma unroll
        for (int t = 0; t < 8; t++) {
            vals[16 + t] = fmaxf(a0[t], 0.f) + c0[t];
            vals[24 + t] = fmaxf(a1[t], 0.f) + c1[t];
        }
    }

    ull pk[16];
#pragma unroll
    for (int p = 0; p < 16; p++) pk[p] = pack2(vals[2 * p], vals[2 * p + 1]);

    const float* Cb = s_C + r * 24 * 36;
    float* outp = out + ((size_t)b * NN + n) * 24;
#pragma unroll 4
    for (int o2 = 0; o2 < 24; o2++) {
        const ulonglong2* cp = (const ulonglong2*)(Cb + o2 * 36);
        ull acc = pack2(Cb[o2 * 36 + 32], 0.f);
#pragma unroll
        for (int p = 0; p < 8; p++) {
            ulonglong2 cc = cp[p];
            acc = fma2(cc.x, pk[2 * p], acc);
            acc = fma2(cc.y, pk[2 * p + 1], acc);
        }
        float lo, hi;
        unpack2(acc, lo, hi);
        outp[o2] = lo + hi;
    }
}

// ---------------------------------------------------------------------------
extern "C" void kernel_launch(void* const* d_in, const int* in_sizes, int n_in,
                              void* d_out, int out_size)
{
    const float* obs      = (const float*)d_in[0];
    const float* obs_vel  = (const float*)d_in[1];
    const float* noise    = (const float*)d_in[2];
    const float* wq_rule  = (const float*)d_in[3];
    const float* bq_rule  = (const float*)d_in[4];
    const float* wq_ctx   = (const float*)d_in[5];
    const float* bq_ctx   = (const float*)d_in[6];
    const float* wk_ctx   = (const float*)d_in[7];
    const float* bk_ctx   = (const float*)d_in[8];
    const float* rule_emb = (const float*)d_in[9];
    const float* w_noise  = (const float*)d_in[10];
    const float* w_indiv  = (const float*)d_in[11];
    const float* w_social = (const float*)d_in[12];
    const float* sp_w  = (const float*)d_in[13];
    const float* sp_b  = (const float*)d_in[14];
    const float* spr_w = (const float*)d_in[15];
    const float* spr_b = (const float*)d_in[16];
    const float* tp_w  = (const float*)d_in[17];
    const float* tp_b  = (const float*)d_in[18];
    const float* tpr_w = (const float*)d_in[19];
    const float* tpr_b = (const float*)d_in[20];
    const float* spi_w  = (const float*)d_in[21];
    const float* spi_b  = (const float*)d_in[22];
    const float* spir_w = (const float*)d_in[23];
    const float* spir_b = (const float*)d_in[24];
    const float* tpi_w  = (const float*)d_in[25];
    const float* tpi_b  = (const float*)d_in[26];
    const float* tpir_w = (const float*)d_in[27];
    const float* tpir_b = (const float*)d_in[28];
    float* out = (float*)d_out;

    static bool attr_set = false;
    if (!attr_set) {
        cudaFuncSetAttribute(kB_hmma, cudaFuncAttributeMaxDynamicSharedMemorySize, 69632);
        attr_set = true;
    }

    kA<<<64, 256>>>(obs, obs_vel, wq_rule, bq_rule, wq_ctx, bq_ctx, wk_ctx, bk_ctx);
    kR<<<32, 128>>>(rule_emb);
    kP<<<1, 192>>>(w_indiv, w_social, tp_w, tp_b, tpr_w, tpr_b,
                   tpi_w, tpi_b, tpir_w, tpir_b);
    kB_hmma<<<dim3(128, 2), 256, 69632>>>();
    kS<<<512, 256>>>();
    kC<<<512, 160>>>(obs_vel, noise, w_noise,
                     sp_w, sp_b, spr_w, spr_b,
                     spi_w, spi_b, spir_w, spir_b, out);
}

// round 10
// speedup vs baseline: 1.5960x; 1.2482x over previous
#include <cuda_runtime.h>
#include <cuda_bf16.h>
#include <cstdint>

#define NN 4096
#define TT 8
#define KTOP 4
#define RR 8
#define DKK 64
#define BB 20

typedef unsigned long long ull;

__device__ __align__(16) float g_q[NN * DKK];
__device__ __align__(16) float g_k[NN * DKK];
__device__ __align__(16) float g_rq[NN * DKK];
__device__ __align__(16) __nv_bfloat16 g_qh[NN * DKK];
__device__ __align__(16) __nv_bfloat16 g_kh[NN * DKK];
__device__ __align__(16) float g_C[RR * 24 * 36];
__device__ __align__(16) ull g_cand2[NN * 128];
__device__ int g_ctx[NN * KTOP];
__device__ int g_rule[NN];

// ---------------- small helpers ----------------
__device__ __forceinline__ ull pack2(float a, float b) {
    ull r;
    asm("mov.b64 %0, {%1, %2};" : "=l"(r) : "f"(a), "f"(b));
    return r;
}
__device__ __forceinline__ void unpack2(ull v, float& a, float& b) {
    asm("mov.b64 {%0, %1}, %2;" : "=f"(a), "=f"(b) : "l"(v));
}
__device__ __forceinline__ ull fma2(ull a, ull b, ull c) {
    ull d;
    asm("fma.rn.f32x2 %0, %1, %2, %3;" : "=l"(d) : "l"(a), "l"(b), "l"(c));
    return d;
}
// unordered keep-4-largest (candidate pool; exact ranking done later in kS)
__device__ __forceinline__ void insU(float v, int c, float* tv, int* ti, float& vmin) {
    if (v > vmin) {
        bool done = false;
#pragma unroll
        for (int j = 0; j < 4; j++) {
            if (!done && tv[j] == vmin) { tv[j] = v; ti[j] = c; done = true; }
        }
        vmin = fminf(fminf(tv[0], tv[1]), fminf(tv[2], tv[3]));
    }
}
__device__ __forceinline__ uint32_t ordf(float v) {
    uint32_t u = __float_as_uint(v);
    return (u & 0x80000000u) ? ~u : (u | 0x80000000u);
}
__device__ __forceinline__ uint32_t smem_to_u32(const void* p) {
    uint32_t a;
    asm("{ .reg .u64 t; cvta.to.shared.u64 t, %1; cvt.u32.u64 %0, t; }" : "=r"(a) : "l"(p));
    return a;
}
#define SWZ(row, byteoff) \
    ((row) * 128 + (((((byteoff) >> 4) ^ ((row) & 7)) << 4)) + ((byteoff) & 15))

// ---------------------------------------------------------------------------
// kA: x[4096x32] @ W[32x192] -> g_q | g_k | g_rq, plus bf16 copies of q,k
// 128 blocks x 256 thr; block = 32 rows; thread = 4 rows x 3 colpairs.
// ---------------------------------------------------------------------------
__global__ __launch_bounds__(256) void kA(
    const float* __restrict__ obs, const float* __restrict__ obs_vel,
    const float* __restrict__ wq_rule, const float* __restrict__ bq_rule,
    const float* __restrict__ wq_ctx, const float* __restrict__ bq_ctx,
    const float* __restrict__ wk_ctx, const float* __restrict__ bk_ctx)
{
    __shared__ __align__(16) ull x2_s[32 * 32];  // [kk][node], dup pairs
    __shared__ __align__(16) ull w_s[32 * 96];   // [kk][colpair]
    int tid = threadIdx.x;
    int n0 = blockIdx.x * 32;

    float* xf = (float*)x2_s;
    for (int e = tid; e < 32 * 32; e += 256) {
        int i = e >> 5, node = e & 31;
        int t = i >> 2, c = i & 3;
        const float* src = (c < 2) ? obs : obs_vel;
        float v = src[(c & 1) * NN * TT + (n0 + node) * TT + t];
        xf[e * 2] = v; xf[e * 2 + 1] = v;
    }
    float* wf = (float*)w_s;
    for (int e = tid; e < 32 * 192; e += 256) {
        int i = e / 192, col = e % 192;
        float v;
        if (col < 64) v = wq_ctx[i * 64 + col];
        else if (col < 128) v = wk_ctx[i * 64 + col - 64];
        else {
            int c = i & 3;
            if (c >= 2) v = wq_rule[((i >> 2) * 2 + (c - 2)) * 64 + (col - 128)];
            else v = 0.f;
        }
        wf[i * 192 + col] = v;
    }
    __syncthreads();

    int w = tid >> 5, tx = tid & 31;
    int rbase = w * 4;
    ull bp[3];
#pragma unroll
    for (int j = 0; j < 3; j++) {
        int c2 = (tx * 3 + j) * 2;
        float b0, b1;
        if (c2 < 64) { b0 = bq_ctx[c2]; b1 = bq_ctx[c2 + 1]; }
        else if (c2 < 128) { b0 = bk_ctx[c2 - 64]; b1 = bk_ctx[c2 - 63]; }
        else { b0 = bq_rule[c2 - 128]; b1 = bq_rule[c2 - 127]; }
        bp[j] = pack2(b0, b1);
    }
    ull acc[4][3];
#pragma unroll
    for (int r = 0; r < 4; r++)
#pragma unroll
        for (int j = 0; j < 3; j++) acc[r][j] = bp[j];

#pragma unroll 8
    for (int kk = 0; kk < 32; kk++) {
        const ulonglong2* qp = (const ulonglong2*)(x2_s + kk * 32 + rbase);
        ulonglong2 q0 = qp[0], q1 = qp[1];
        ull qr[4] = { q0.x, q0.y, q1.x, q1.y };
        ull wv0 = w_s[kk * 96 + tx * 3 + 0];
        ull wv1 = w_s[kk * 96 + tx * 3 + 1];
        ull wv2 = w_s[kk * 96 + tx * 3 + 2];
#pragma unroll
        for (int r = 0; r < 4; r++) {
            acc[r][0] = fma2(qr[r], wv0, acc[r][0]);
            acc[r][1] = fma2(qr[r], wv1, acc[r][1]);
            acc[r][2] = fma2(qr[r], wv2, acc[r][2]);
        }
    }
#pragma unroll
    for (int r = 0; r < 4; r++) {
        int node = n0 + rbase + r;
#pragma unroll
        for (int j = 0; j < 3; j++) {
            int c2 = (tx * 3 + j) * 2;
            float v0, v1;
            unpack2(acc[r][j], v0, v1);
            int cc = c2 & 63;
            if (c2 < 64) {
                g_q[node * 64 + cc] = v0;
                g_q[node * 64 + cc + 1] = v1;
                *(__nv_bfloat162*)&g_qh[node * 64 + cc] = __floats2bfloat162_rn(v0, v1);
            } else if (c2 < 128) {
                g_k[node * 64 + cc] = v0;
                g_k[node * 64 + cc + 1] = v1;
                *(__nv_bfloat162*)&g_kh[node * 64 + cc] = __floats2bfloat162_rn(v0, v1);
            } else {
                g_rq[node * 64 + cc] = v0;
                g_rq[node * 64 + cc + 1] = v1;
            }
        }
    }
}

// ---------------------------------------------------------------------------
// kR: rule argmax from g_rq @ rule_emb^T
// ---------------------------------------------------------------------------
__global__ __launch_bounds__(128) void kR(const float* __restrict__ rule_emb)
{
    __shared__ float s_emb[64 * 8];
    int tid = threadIdx.x;
    for (int e = tid; e < 512; e += 128) s_emb[e] = rule_emb[(e & 7) * 64 + (e >> 3)];
    __syncthreads();
    int n = blockIdx.x * 128 + tid;
    float lg[8];
#pragma unroll
    for (int r = 0; r < 8; r++) lg[r] = 0.f;
#pragma unroll
    for (int og = 0; og < 16; og++) {
        float4 v = *(const float4*)&g_rq[n * 64 + og * 4];
        float vv[4] = { v.x, v.y, v.z, v.w };
#pragma unroll
        for (int e = 0; e < 4; e++) {
            int o = og * 4 + e;
#pragma unroll
            for (int r = 0; r < 8; r++) lg[r] = fmaf(vv[e], s_emb[o * 8 + r], lg[r]);
        }
    }
    int best = 0;
    float bv = lg[0];
#pragma unroll
    for (int r = 1; r < 8; r++)
        if (lg[r] > bv) { bv = lg[r]; best = r; }
    g_rule[n] = best;
}

// ---------------------------------------------------------------------------
// kB_hmma: scores via mma.sync bf16 HMMA + per-thread keep-4 candidates,
// written as packed (orderable-value, ~idx) u64 keys for kS prefiltering.
// grid (128 rowblocks, 2 colsplits) x 256 thr.
// ---------------------------------------------------------------------------
__global__ __launch_bounds__(256, 3) void kB_hmma()
{
    extern __shared__ char smem[];
    char* As = smem;               // 32 x 128B
    char* Bs0 = smem + 4096;       // 256 x 128B
    char* Bs1 = smem + 4096 + 32768;
    int tid = threadIdx.x, lane = tid & 31, wid = tid >> 5;
    int row0 = blockIdx.x * 32;
    int split = blockIdx.y;
    int colbase = split * 2048;

    // stage A (swizzled): 32 rows x 8 chunks = 256
    {
        int r = tid >> 3, c = tid & 7;
        uint4 v = *(const uint4*)((const char*)g_qh + (size_t)(row0 + r) * 128 + c * 16);
        *(uint4*)(As + r * 128 + ((c ^ (r & 7)) << 4)) = v;
    }
    // prefetch B tile 0
    {
        int r = tid;
        const char* src = (const char*)g_kh + (size_t)(colbase + r) * 128;
        char* dst = Bs0 + r * 128;
#pragma unroll
        for (int c = 0; c < 8; c++) {
            uint32_t daddr = smem_to_u32(dst + ((c ^ (r & 7)) << 4));
            asm volatile("cp.async.cg.shared.global [%0], [%1], 16;"
                         :: "r"(daddr), "l"(src + c * 16));
        }
        asm volatile("cp.async.commit_group;");
    }
    __syncthreads();

    int rg = wid >> 2, ch = wid & 3;
    int m0 = rg * 16;

    uint32_t a[4][4];
    {
        int arow = m0 + (lane & 15);
        int kbh = ((lane >> 4) & 1) * 16;
#pragma unroll
        for (int k = 0; k < 4; k++) {
            int byteoff = k * 32 + kbh;
            uint32_t addr = smem_to_u32(As + SWZ(arow, byteoff));
            asm volatile("ldmatrix.sync.aligned.m8n8.x4.shared.b16 {%0,%1,%2,%3}, [%4];"
                : "=r"(a[k][0]), "=r"(a[k][1]), "=r"(a[k][2]), "=r"(a[k][3]) : "r"(addr));
        }
    }

    int brow_off = (lane & 7) + ((lane & 16) >> 1);
    int bkb = (lane & 8) ? 16 : 0;

    float tv[2][4];
    int ti[2][4];
    float vmin0 = -3.4e38f, vmin1 = -3.4e38f;
#pragma unroll
    for (int h = 0; h < 2; h++)
#pragma unroll
        for (int j = 0; j < 4; j++) { tv[h][j] = -3.4e38f; ti[h][j] = 0; }

    for (int t = 0; t < 8; t++) {
        if (t < 7) {
            char* dst0 = ((t + 1) & 1) ? Bs1 : Bs0;
            int r = tid;
            const char* src = (const char*)g_kh + (size_t)(colbase + (t + 1) * 256 + r) * 128;
            char* dst = dst0 + r * 128;
#pragma unroll
            for (int c = 0; c < 8; c++) {
                uint32_t daddr = smem_to_u32(dst + ((c ^ (r & 7)) << 4));
                asm volatile("cp.async.cg.shared.global [%0], [%1], 16;"
                             :: "r"(daddr), "l"(src + c * 16));
            }
            asm volatile("cp.async.commit_group;");
            asm volatile("cp.async.wait_group 1;");
        } else {
            asm volatile("cp.async.wait_group 0;");
        }
        __syncthreads();

        const char* B = (t & 1) ? Bs1 : Bs0;
        int coltile = colbase + t * 256;
#pragma unroll
        for (int np = 0; np < 4; np++) {
            int n0 = ch * 64 + np * 16;
            uint32_t b[4][4];
#pragma unroll
            for (int k = 0; k < 4; k++) {
                int brow = n0 + brow_off;
                int byteoff = k * 32 + bkb;
                uint32_t addr = smem_to_u32(B + SWZ(brow, byteoff));
                asm volatile("ldmatrix.sync.aligned.m8n8.x4.shared.b16 {%0,%1,%2,%3}, [%4];"
                    : "=r"(b[k][0]), "=r"(b[k][1]), "=r"(b[k][2]), "=r"(b[k][3]) : "r"(addr));
            }
            float c0[4] = {0.f, 0.f, 0.f, 0.f};
            float c1[4] = {0.f, 0.f, 0.f, 0.f};
#pragma unroll
            for (int k = 0; k < 4; k++) {
                asm volatile(
                    "mma.sync.aligned.m16n8k16.row.col.f32.bf16.bf16.f32 "
                    "{%0,%1,%2,%3}, {%4,%5,%6,%7}, {%8,%9}, {%0,%1,%2,%3};"
                    : "+f"(c0[0]), "+f"(c0[1]), "+f"(c0[2]), "+f"(c0[3])
                    : "r"(a[k][0]), "r"(a[k][1]), "r"(a[k][2]), "r"(a[k][3]),
                      "r"(b[k][0]), "r"(b[k][1]));
                asm volatile(
                    "mma.sync.aligned.m16n8k16.row.col.f32.bf16.bf16.f32 "
                    "{%0,%1,%2,%3}, {%4,%5,%6,%7}, {%8,%9}, {%0,%1,%2,%3};"
                    : "+f"(c1[0]), "+f"(c1[1]), "+f"(c1[2]), "+f"(c1[3])
                    : "r"(a[k][0]), "r"(a[k][1]), "r"(a[k][2]), "r"(a[k][3]),
                      "r"(b[k][2]), "r"(b[k][3]));
            }
            int colg = coltile + n0 + 2 * (lane & 3);
            float m0v = fmaxf(fmaxf(c0[0], c0[1]), fmaxf(c1[0], c1[1]));
            if (m0v > vmin0) {
                insU(c0[0], colg, tv[0], ti[0], vmin0);
                insU(c0[1], colg + 1, tv[0], ti[0], vmin0);
                insU(c1[0], colg + 8, tv[0], ti[0], vmin0);
                insU(c1[1], colg + 9, tv[0], ti[0], vmin0);
            }
            float m1v = fmaxf(fmaxf(c0[2], c0[3]), fmaxf(c1[2], c1[3]));
            if (m1v > vmin1) {
                insU(c0[2], colg, tv[1], ti[1], vmin1);
                insU(c0[3], colg + 1, tv[1], ti[1], vmin1);
                insU(c1[2], colg + 8, tv[1], ti[1], vmin1);
                insU(c1[3], colg + 9, tv[1], ti[1], vmin1);
            }
        }
        __syncthreads();
    }

    // write packed candidate keys: 16 threads/row (4 ch-warps x 4 lanes)
    int slot = ch * 4 + (lane & 3);
    int rlo = row0 + m0 + (lane >> 2);
#pragma unroll
    for (int h = 0; h < 2; h++) {
        int row = rlo + h * 8;
        size_t base = (size_t)row * 128 + split * 64 + slot * 4;
#pragma unroll
        for (int j = 0; j < 4; j++) {
            ull key = ((ull)ordf(tv[h][j]) << 32) | (uint32_t)(~ti[h][j]);
            g_cand2[base + j] = key;
        }
    }
}

// ---------------------------------------------------------------------------
// kS: warp per row. Load 128 approx keys, warp-select approx top-16, exact
// fp32 rescore of those 16, exact tie-correct top-4 -> g_ctx.
// ---------------------------------------------------------------------------
__global__ __launch_bounds__(256) void kS()
{
    int tid = threadIdx.x, lane = tid & 31, wid = tid >> 5;
    int row = blockIdx.x * 8 + wid;

    ull key[4];
    {
        const ulonglong2* cp = (const ulonglong2*)&g_cand2[(size_t)row * 128];
        ulonglong2 ka = cp[lane * 2], kb = cp[lane * 2 + 1];
        key[0] = ka.x; key[1] = ka.y; key[2] = kb.x; key[3] = kb.y;
    }

    // approx top-16: 16 rounds of warp max-reduce; round r's winner -> lane r
    int myIdx = 0;
#pragma unroll
    for (int r = 0; r < 16; r++) {
        ull best = key[0];
#pragma unroll
        for (int j = 1; j < 4; j++) best = (key[j] > best) ? key[j] : best;
#pragma unroll
        for (int off = 16; off; off >>= 1) {
            ull o = __shfl_xor_sync(0xffffffff, best, off);
            if (o > best) best = o;
        }
        if (lane == r) myIdx = (int)(~(uint32_t)best);
#pragma unroll
        for (int j = 0; j < 4; j++)
            if (key[j] == best) key[j] = 0;
    }

    // exact rescore on lanes 0..15 (reference accumulation order)
    ull ek = 0;
    if (lane < 16) {
        const float4* qp = (const float4*)&g_q[(size_t)row * 64];
        const float4* kp = (const float4*)&g_k[(size_t)myIdx * 64];
        float acc = 0.f;
#pragma unroll
        for (int i = 0; i < 16; i++) {
            float4 qv = qp[i];
            float4 kv = kp[i];
            acc = fmaf(qv.x, kv.x, acc);
            acc = fmaf(qv.y, kv.y, acc);
            acc = fmaf(qv.z, kv.z, acc);
            acc = fmaf(qv.w, kv.w, acc);
        }
        ek = ((ull)ordf(acc) << 32) | (uint32_t)(~myIdx);
    }
#pragma unroll
    for (int r4 = 0; r4 < 4; r4++) {
        ull best = ek;
#pragma unroll
        for (int off = 16; off; off >>= 1) {
            ull o = __shfl_xor_sync(0xffffffff, best, off);
            if (o > best) best = o;
        }
        if (lane == 0) g_ctx[row * 4 + r4] = (int)(~(uint32_t)best);
        if (ek == best) ek = 0;
    }
}

// ---------------------------------------------------------------------------
// kP: precompute rule-combined time-conv matrices C[r][24][36]
// ---------------------------------------------------------------------------
__global__ void kP(
    const float* __restrict__ w_indiv, const float* __restrict__ w_social,
    const float* __restrict__ tp_w, const float* __restrict__ tp_b,
    const float* __restrict__ tpr_w, const float* __restrict__ tpr_b,
    const float* __restrict__ tpi_w, const float* __restrict__ tpi_b,
    const float* __restrict__ tpir_w, const float* __restrict__ tpir_b)
{
    int t = threadIdx.x;
    if (t >= 192) return;
    int r = t / 24, o2 = t % 24, o = o2 >> 1, pos = o2 & 1;
    float wi = w_indiv[r], ws = w_social[r];
    float* dst = g_C + (r * 24 + o2) * 36;
#pragma unroll
    for (int c = 0; c < 8; c++) {
        int wb = (r * 12 + o) * 8 + c;
        const float* wt = tpi_w + wb * 3;
        float wri = tpir_w[wb];
        float ci0 = pos == 0 ? (wt[1] + wri) : wt[0];
        float ci1 = pos == 0 ? wt[2] : (wt[1] + wri);
        dst[c] = wi * ci0;
        dst[8 + c] = wi * ci1;
        const float* ut = tp_w + wb * 3;
        float urs = tpr_w[wb];
        float cs0 = pos == 0 ? (ut[1] + urs) : ut[0];
        float cs1 = pos == 0 ? ut[2] : (ut[1] + urs);
        dst[16 + c] = ws * cs0;
        dst[24 + c] = ws * cs1;
    }
    dst[32] = wi * (tpi_b[r * 12 + o] + tpir_b[r * 12 + o])
            + ws * (tp_b[r * 12 + o] + tpr_b[r * 12 + o]);
    dst[33] = 0.f; dst[34] = 0.f; dst[35] = 0.f;
}

// ---------------------------------------------------------------------------
// kC: gather + selected-rule spatial convs + combined matvec. 8 nodes x 20 b.
// ---------------------------------------------------------------------------
__global__ __launch_bounds__(160) void kC(
    const float* __restrict__ obs_vel, const float* __restrict__ noise,
    const float* __restrict__ w_noise,
    const float* __restrict__ sp_w, const float* __restrict__ sp_b,
    const float* __restrict__ spr_w, const float* __restrict__ spr_b,
    const float* __restrict__ spi_w, const float* __restrict__ spi_b,
    const float* __restrict__ spir_w, const float* __restrict__ spir_b,
    float* __restrict__ out)
{
    __shared__ __align__(16) float s_C[8 * 24 * 36];
    __shared__ float s_sp_w[480], s_sp_b[16], s_spr_w[160], s_spr_b[16];
    __shared__ float s_spi_w[96], s_spi_b[16], s_spir_w[32], s_spir_b[16];
    __shared__ float s_wn[8], s_noise[BB * 2];
    __shared__ float s_ov[128], s_cvx[512];
    __shared__ int s_rule[8];

    int tid = threadIdx.x;
    int n0 = blockIdx.x * 8;

    for (int i = tid; i < 8 * 24 * 36; i += 160) s_C[i] = g_C[i];
    for (int i = tid; i < 480; i += 160) s_sp_w[i] = sp_w[i];
    if (tid < 160) s_spr_w[tid] = spr_w[tid];
    if (tid < 96) s_spi_w[tid] = spi_w[tid];
    if (tid < 32) s_spir_w[tid] = spir_w[tid];
    if (tid < 16) {
        s_sp_b[tid] = sp_b[tid]; s_spr_b[tid] = spr_b[tid];
        s_spi_b[tid] = spi_b[tid]; s_spir_b[tid] = spir_b[tid];
    }
    if (tid < 8) { s_wn[tid] = w_noise[tid]; s_rule[tid] = g_rule[n0 + tid]; }
    if (tid < 40) s_noise[tid] = noise[tid];
    for (int i = tid; i < 128; i += 160) {
        int node = i >> 4, s = (i >> 3) & 1, t = i & 7;
        s_ov[i] = obs_vel[s * NN * TT + (n0 + node) * TT + t];
    }
    for (int i = tid; i < 512; i += 160) {
        int node = i >> 6, rem = i & 63, k = rem >> 4, s = (rem >> 3) & 1, t = rem & 7;
        int nb = g_ctx[(n0 + node) * 4 + k];
        s_cvx[i] = obs_vel[s * NN * TT + nb * TT + t];
    }
    __syncthreads();

    int node = tid / 20, b = tid - node * 20;
    int n = n0 + node;
    int r = s_rule[node];
    float wn = s_wn[r];
    float nz0 = s_noise[b * 2 + 0] * wn;
    float nz1 = s_noise[b * 2 + 1] * wn;

    float v0[8], v1[8];
#pragma unroll
    for (int t = 0; t < 8; t++) {
        v0[t] = s_ov[node * 16 + t] + nz0;
        v1[t] = s_ov[node * 16 + 8 + t] + nz1;
    }

    float vals[32];

    {
        const float* pw3 = s_spi_w + r * 12;
        const float* pw1 = s_spir_w + r * 4;
#pragma unroll
    for (int so = 0; so < 2; so++) {
            float b3 = s_spi_b[r * 2 + so], b1 = s_spir_b[r * 2 + so];
            float w00 = pw3[so * 6 + 0], w01 = pw3[so * 6 + 1], w02 = pw3[so * 6 + 2];
            float w10 = pw3[so * 6 + 3], w11 = pw3[so * 6 + 4], w12 = pw3[so * 6 + 5];
            float wr0 = pw1[so * 2 + 0], wr1 = pw1[so * 2 + 1];
#pragma unroll
            for (int t = 0; t < 8; t++) {
                float a = b3;
                a = fmaf(w01, v0[t], a);
                a = fmaf(w11, v1[t], a);
                if (t > 0) { a = fmaf(w00, v0[t - 1], a); a = fmaf(w10, v1[t - 1], a); }
                if (t < 7) { a = fmaf(w02, v0[t + 1], a); a = fmaf(w12, v1[t + 1], a); }
                a = fmaxf(a, 0.f);
                float c1 = b1;
                c1 = fmaf(wr0, v0[t], c1);
                c1 = fmaf(wr1, v1[t], c1);
                vals[so * 8 + t] = a + c1;
            }
        }
    }

    {
        float a0[8], a1[8], c0[8], c1[8];
        float ba0 = s_sp_b[r * 2], ba1 = s_sp_b[r * 2 + 1];
        float bc0 = s_spr_b[r * 2], bc1 = s_spr_b[r * 2 + 1];
#pragma unroll
        for (int t = 0; t < 8; t++) { a0[t] = ba0; a1[t] = ba1; c0[t] = bc0; c1[t] = bc1; }
        const float* q3 = s_sp_w + r * 60;
        const float* q1 = s_spr_w + r * 20;

#define PROC_CH(ci, VV)                                                        \
        {                                                                      \
            float u0 = q3[(ci) * 3], u1 = q3[(ci) * 3 + 1], u2 = q3[(ci) * 3 + 2]; \
            float z0 = q3[30 + (ci) * 3], z1 = q3[30 + (ci) * 3 + 1], z2 = q3[30 + (ci) * 3 + 2]; \
            float ur = q1[(ci)], zr = q1[10 + (ci)];                           \
            _Pragma("unroll")                                                  \
            for (int t = 0; t < 8; t++) {                                      \
                float x = VV[t];                                               \
                a0[t] = fmaf(u1, x, a0[t]); a1[t] = fmaf(z1, x, a1[t]);        \
                c0[t] = fmaf(ur, x, c0[t]); c1[t] = fmaf(zr, x, c1[t]);        \
                if (t > 0) { a0[t] = fmaf(u0, VV[t - 1], a0[t]); a1[t] = fmaf(z0, VV[t - 1], a1[t]); } \
                if (t < 7) { a0[t] = fmaf(u2, VV[t + 1], a0[t]); a1[t] = fmaf(z2, VV[t + 1], a1[t]); } \
            }                                                                  \
        }

        PROC_CH(0, v0)
        PROC_CH(1, v1)
#pragma unroll
        for (int k = 0; k < 4; k++) {
            float nb0[8], nb1[8];
#pragma unroll
            for (int t = 0; t < 8; t++) {
                nb0[t] = s_cvx[node * 64 + k * 16 + t] + nz0;
                nb1[t] = s_cvx[node * 64 + k * 16 + 8 + t] + nz1;
            }
            PROC_CH(2 + k * 2 + 0, nb0)
            PROC_CH(2 + k * 2 + 1, nb1)
        }
#undef PROC_CH
#pragma unroll
        for (int t = 0; t < 8; t++) {
            vals[16 + t] = fmaxf(a0[t], 0.f) + c0[t];
            vals[24 + t] = fmaxf(a1[t], 0.f) + c1[t];
        }
    }

    ull pk[16];
#pragma unroll
    for (int p = 0; p < 16; p++) pk[p] = pack2(vals[2 * p], vals[2 * p + 1]);

    const float* Cb = s_C + r * 24 * 36;
    float* outp = out + ((size_t)b * NN + n) * 24;
#pragma unroll 4
    for (int o2 = 0; o2 < 24; o2++) {
        const ulonglong2* cp = (const ulonglong2*)(Cb + o2 * 36);
        ull acc = pack2(Cb[o2 * 36 + 32], 0.f);
#pragma unroll
        for (int p = 0; p < 8; p++) {
            ulonglong2 cc = cp[p];
            acc = fma2(cc.x, pk[2 * p], acc);
            acc = fma2(cc.y, pk[2 * p + 1], acc);
        }
        float lo, hi;
        unpack2(acc, lo, hi);
        outp[o2] = lo + hi;
    }
}

// ---------------------------------------------------------------------------
extern "C" void kernel_launch(void* const* d_in, const int* in_sizes, int n_in,
                              void* d_out, int out_size)
{
    const float* obs      = (const float*)d_in[0];
    const float* obs_vel  = (const float*)d_in[1];
    const float* noise    = (const float*)d_in[2];
    const float* wq_rule  = (const float*)d_in[3];
    const float* bq_rule  = (const float*)d_in[4];
    const float* wq_ctx   = (const float*)d_in[5];
    const float* bq_ctx   = (const float*)d_in[6];
    const float* wk_ctx   = (const float*)d_in[7];
    const float* bk_ctx   = (const float*)d_in[8];
    const float* rule_emb = (const float*)d_in[9];
    const float* w_noise  = (const float*)d_in[10];
    const float* w_indiv  = (const float*)d_in[11];
    const float* w_social = (const float*)d_in[12];
    const float* sp_w  = (const float*)d_in[13];
    const float* sp_b  = (const float*)d_in[14];
    const float* spr_w = (const float*)d_in[15];
    const float* spr_b = (const float*)d_in[16];
    const float* tp_w  = (const float*)d_in[17];
    const float* tp_b  = (const float*)d_in[18];
    const float* tpr_w = (const float*)d_in[19];
    const float* tpr_b = (const float*)d_in[20];
    const float* spi_w  = (const float*)d_in[21];
    const float* spi_b  = (const float*)d_in[22];
    const float* spir_w = (const float*)d_in[23];
    const float* spir_b = (const float*)d_in[24];
    const float* tpi_w  = (const float*)d_in[25];
    const float* tpi_b  = (const float*)d_in[26];
    const float* tpir_w = (const float*)d_in[27];
    const float* tpir_b = (const float*)d_in[28];
    float* out = (float*)d_out;

    static bool attr_set = false;
    if (!attr_set) {
        cudaFuncSetAttribute(kB_hmma, cudaFuncAttributeMaxDynamicSharedMemorySize, 69632);
        attr_set = true;
    }

    kA<<<128, 256>>>(obs, obs_vel, wq_rule, bq_rule, wq_ctx, bq_ctx, wk_ctx, bk_ctx);
    kR<<<32, 128>>>(rule_emb);
    kP<<<1, 192>>>(w_indiv, w_social, tp_w, tp_b, tpr_w, tpr_b,
                   tpi_w, tpi_b, tpir_w, tpir_b);
    kB_hmma<<<dim3(128, 2), 256, 69632>>>();
    kS<<<512, 256>>>();
    kC<<<512, 160>>>(obs_vel, noise, w_noise,
                     sp_w, sp_b, spr_w, spr_b,
                     spi_w, spi_b, spir_w, spir_b, out);
}

// round 12
// speedup vs baseline: 1.6447x; 1.0305x over previous
#include <cuda_runtime.h>
#include <cuda_bf16.h>
#include <cstdint>

#define NN 4096
#define TT 8
#define KTOP 4
#define RR 8
#define DKK 64
#define BB 20

typedef unsigned long long ull;

__device__ __align__(16) float g_q[NN * DKK];
__device__ __align__(16) float g_k[NN * DKK];
__device__ __align__(16) __nv_bfloat16 g_qh[NN * DKK];
__device__ __align__(16) __nv_bfloat16 g_kh[NN * DKK];
__device__ __align__(16) float g_C[RR * 24 * 36];
__device__ __align__(16) float g_NZ[RR * 32];
__device__ __align__(16) ull g_cand2[NN * 128];
__device__ int g_ctx[NN * KTOP];
__device__ int g_rule[NN];

// ---------------- small helpers ----------------
__device__ __forceinline__ ull pack2(float a, float b) {
    ull r;
    asm("mov.b64 %0, {%1, %2};" : "=l"(r) : "f"(a), "f"(b));
    return r;
}
__device__ __forceinline__ void unpack2(ull v, float& a, float& b) {
    asm("mov.b64 {%0, %1}, %2;" : "=f"(a), "=f"(b) : "l"(v));
}
__device__ __forceinline__ ull fma2(ull a, ull b, ull c) {
    ull d;
    asm("fma.rn.f32x2 %0, %1, %2, %3;" : "=l"(d) : "l"(a), "l"(b), "l"(c));
    return d;
}
__device__ __forceinline__ void insU(float v, int c, float* tv, int* ti, float& vmin) {
    if (v > vmin) {
        bool done = false;
#pragma unroll
        for (int j = 0; j < 4; j++) {
            if (!done && tv[j] == vmin) { tv[j] = v; ti[j] = c; done = true; }
        }
        vmin = fminf(fminf(tv[0], tv[1]), fminf(tv[2], tv[3]));
    }
}
__device__ __forceinline__ uint32_t ordf(float v) {
    uint32_t u = __float_as_uint(v);
    return (u & 0x80000000u) ? ~u : (u | 0x80000000u);
}
__device__ __forceinline__ uint32_t smem_to_u32(const void* p) {
    uint32_t a;
    asm("{ .reg .u64 t; cvta.to.shared.u64 t, %1; cvt.u32.u64 %0, t; }" : "=r"(a) : "l"(p));
    return a;
}
#define SWZ(row, byteoff) \
    ((row) * 128 + (((((byteoff) >> 4) ^ ((row) & 7)) << 4)) + ((byteoff) & 15))

// ---------------------------------------------------------------------------
// kA: x[4096x32] @ W[32x192] -> g_q | g_k | rq(smem), + fused rule argmax.
// 128 blocks x 256 thr; block = 32 rows.
// ---------------------------------------------------------------------------
__global__ __launch_bounds__(256) void kA(
    const float* __restrict__ obs, const float* __restrict__ obs_vel,
    const float* __restrict__ wq_rule, const float* __restrict__ bq_rule,
    const float* __restrict__ wq_ctx, const float* __restrict__ bq_ctx,
    const float* __restrict__ wk_ctx, const float* __restrict__ bk_ctx,
    const float* __restrict__ rule_emb)
{
    __shared__ __align__(16) ull x2_s[32 * 32];  // [kk][node], dup pairs
    __shared__ __align__(16) ull w_s[32 * 96];   // [kk][colpair]
    __shared__ float s_rqv[32 * 64];
    __shared__ float s_lg[32 * 8];
    __shared__ float s_emb[64 * 8];
    int tid = threadIdx.x;
    int n0 = blockIdx.x * 32;

    float* xf = (float*)x2_s;
    for (int e = tid; e < 32 * 32; e += 256) {
        int i = e >> 5, node = e & 31;
        int t = i >> 2, c = i & 3;
        const float* src = (c < 2) ? obs : obs_vel;
        float v = src[(c & 1) * NN * TT + (n0 + node) * TT + t];
        xf[e * 2] = v; xf[e * 2 + 1] = v;
    }
    float* wf = (float*)w_s;
    for (int e = tid; e < 32 * 192; e += 256) {
        int i = e / 192, col = e % 192;
        float v;
        if (col < 64) v = wq_ctx[i * 64 + col];
        else if (col < 128) v = wk_ctx[i * 64 + col - 64];
        else {
            int c = i & 3;
            if (c >= 2) v = wq_rule[((i >> 2) * 2 + (c - 2)) * 64 + (col - 128)];
            else v = 0.f;
        }
        wf[i * 192 + col] = v;
    }
    for (int e = tid; e < 512; e += 256) s_emb[e] = rule_emb[(e & 7) * 64 + (e >> 3)];
    __syncthreads();

    int w = tid >> 5, tx = tid & 31;
    int rbase = w * 4;
    ull bp[3];
#pragma unroll
    for (int j = 0; j < 3; j++) {
        int c2 = (tx * 3 + j) * 2;
        float b0, b1;
        if (c2 < 64) { b0 = bq_ctx[c2]; b1 = bq_ctx[c2 + 1]; }
        else if (c2 < 128) { b0 = bk_ctx[c2 - 64]; b1 = bk_ctx[c2 - 63]; }
        else { b0 = bq_rule[c2 - 128]; b1 = bq_rule[c2 - 127]; }
        bp[j] = pack2(b0, b1);
    }
    ull acc[4][3];
#pragma unroll
    for (int r = 0; r < 4; r++)
#pragma unroll
        for (int j = 0; j < 3; j++) acc[r][j] = bp[j];

#pragma unroll 8
    for (int kk = 0; kk < 32; kk++) {
        const ulonglong2* qp = (const ulonglong2*)(x2_s + kk * 32 + rbase);
        ulonglong2 q0 = qp[0], q1 = qp[1];
        ull qr[4] = { q0.x, q0.y, q1.x, q1.y };
        ull wv0 = w_s[kk * 96 + tx * 3 + 0];
        ull wv1 = w_s[kk * 96 + tx * 3 + 1];
        ull wv2 = w_s[kk * 96 + tx * 3 + 2];
#pragma unroll
        for (int r = 0; r < 4; r++) {
            acc[r][0] = fma2(qr[r], wv0, acc[r][0]);
            acc[r][1] = fma2(qr[r], wv1, acc[r][1]);
            acc[r][2] = fma2(qr[r], wv2, acc[r][2]);
        }
    }
#pragma unroll
    for (int r = 0; r < 4; r++) {
        int nodeL = rbase + r;
        int node = n0 + nodeL;
#pragma unroll
        for (int j = 0; j < 3; j++) {
            int c2 = (tx * 3 + j) * 2;
            float v0, v1;
            unpack2(acc[r][j], v0, v1);
            int cc = c2 & 63;
            if (c2 < 64) {
                g_q[node * 64 + cc] = v0;
                g_q[node * 64 + cc + 1] = v1;
                *(__nv_bfloat162*)&g_qh[node * 64 + cc] = __floats2bfloat162_rn(v0, v1);
            } else if (c2 < 128) {
                g_k[node * 64 + cc] = v0;
                g_k[node * 64 + cc + 1] = v1;
                *(__nv_bfloat162*)&g_kh[node * 64 + cc] = __floats2bfloat162_rn(v0, v1);
            } else {
                s_rqv[nodeL * 64 + cc] = v0;
                s_rqv[nodeL * 64 + cc + 1] = v1;
            }
        }
    }
    __syncthreads();
    // fused rule logits: thread = node(32) x r(8)
    {
        int node = tid >> 3, rr = tid & 7;
        float a = 0.f;
        const float* rv = s_rqv + node * 64;
#pragma unroll 8
        for (int o = 0; o < 64; o++) a = fmaf(rv[o], s_emb[o * 8 + rr], a);
        s_lg[node * 8 + rr] = a;
    }
    __syncthreads();
    if (tid < 32) {
        const float* lg = s_lg + tid * 8;
        int best = 0;
        float bv = lg[0];
#pragma unroll
        for (int r = 1; r < 8; r++)
            if (lg[r] > bv) { bv = lg[r]; best = r; }
        g_rule[n0 + tid] = best;
    }
}

// ---------------------------------------------------------------------------
// kB_hmma: scores via mma.sync bf16 HMMA + per-thread keep-4 candidates
// (packed u64 keys). grid (128 rowblocks, 2 colsplits) x 256 thr.
// Single __syncthreads per tile; fully unrolled tile loop.
// ---------------------------------------------------------------------------
__global__ __launch_bounds__(256, 3) void kB_hmma()
{
    extern __shared__ char smem[];
    char* As = smem;               // 32 x 128B
    char* Bs0 = smem + 4096;       // 256 x 128B
    char* Bs1 = smem + 4096 + 32768;
    int tid = threadIdx.x, lane = tid & 31, wid = tid >> 5;
    int row0 = blockIdx.x * 32;
    int split = blockIdx.y;
    int colbase = split * 2048;

    // stage A (swizzled): 32 rows x 8 chunks = 256
    {
        int r = tid >> 3, c = tid & 7;
        uint4 v = *(const uint4*)((const char*)g_qh + (size_t)(row0 + r) * 128 + c * 16);
        *(uint4*)(As + r * 128 + ((c ^ (r & 7)) << 4)) = v;
    }
    // prefetch B tile 0
    {
        int r = tid;
        const char* src = (const char*)g_kh + (size_t)(colbase + r) * 128;
        char* dst = Bs0 + r * 128;
#pragma unroll
        for (int c = 0; c < 8; c++) {
            uint32_t daddr = smem_to_u32(dst + ((c ^ (r & 7)) << 4));
            asm volatile("cp.async.cg.shared.global [%0], [%1], 16;"
                         :: "r"(daddr), "l"(src + c * 16));
        }
        asm volatile("cp.async.commit_group;");
    }
    __syncthreads();

    int rg = wid >> 2, ch = wid & 3;
    int m0 = rg * 16;

    uint32_t a[4][4];
    {
        int arow = m0 + (lane & 15);
        int kbh = ((lane >> 4) & 1) * 16;
#pragma unroll
        for (int k = 0; k < 4; k++) {
            int byteoff = k * 32 + kbh;
            uint32_t addr = smem_to_u32(As + SWZ(arow, byteoff));
            asm volatile("ldmatrix.sync.aligned.m8n8.x4.shared.b16 {%0,%1,%2,%3}, [%4];"
                : "=r"(a[k][0]), "=r"(a[k][1]), "=r"(a[k][2]), "=r"(a[k][3]) : "r"(addr));
        }
    }

    int brow_off = (lane & 7) + ((lane & 16) >> 1);
    int bkb = (lane & 8) ? 16 : 0;

    float tv[2][4];
    int ti[2][4];
    float vmin0 = -3.4e38f, vmin1 = -3.4e38f;
#pragma unroll
    for (int h = 0; h < 2; h++)
#pragma unroll
        for (int j = 0; j < 4; j++) { tv[h][j] = -3.4e38f; ti[h][j] = 0; }

#pragma unroll
    for (int t = 0; t < 8; t++) {
        asm volatile("cp.async.wait_group 0;");
        __syncthreads();
        if (t < 7) {
            char* dst0 = ((t + 1) & 1) ? Bs1 : Bs0;
            int r = tid;
            const char* src = (const char*)g_kh + (size_t)(colbase + (t + 1) * 256 + r) * 128;
            char* dst = dst0 + r * 128;
#pragma unroll
            for (int c = 0; c < 8; c++) {
                uint32_t daddr = smem_to_u32(dst + ((c ^ (r & 7)) << 4));
                asm volatile("cp.async.cg.shared.global [%0], [%1], 16;"
                             :: "r"(daddr), "l"(src + c * 16));
            }
            asm volatile("cp.async.commit_group;");
        }

        const char* B = (t & 1) ? Bs1 : Bs0;
        int coltile = colbase + t * 256;
#pragma unroll
        for (int np = 0; np < 4; np++) {
            int n0 = ch * 64 + np * 16;
            uint32_t b[4][4];
#pragma unroll
            for (int k = 0; k < 4; k++) {
                int brow = n0 + brow_off;
                int byteoff = k * 32 + bkb;
                uint32_t addr = smem_to_u32(B + SWZ(brow, byteoff));
                asm volatile("ldmatrix.sync.aligned.m8n8.x4.shared.b16 {%0,%1,%2,%3}, [%4];"
                    : "=r"(b[k][0]), "=r"(b[k][1]), "=r"(b[k][2]), "=r"(b[k][3]) : "r"(addr));
            }
            float c0[4] = {0.f, 0.f, 0.f, 0.f};
            float c1[4] = {0.f, 0.f, 0.f, 0.f};
#pragma unroll
            for (int k = 0; k < 4; k++) {
                asm volatile(
                    "mma.sync.aligned.m16n8k16.row.col.f32.bf16.bf16.f32 "
                    "{%0,%1,%2,%3}, {%4,%5,%6,%7}, {%8,%9}, {%0,%1,%2,%3};"
                    : "+f"(c0[0]), "+f"(c0[1]), "+f"(c0[2]), "+f"(c0[3])
                    : "r"(a[k][0]), "r"(a[k][1]), "r"(a[k][2]), "r"(a[k][3]),
                      "r"(b[k][0]), "r"(b[k][1]));
                asm volatile(
                    "mma.sync.aligned.m16n8k16.row.col.f32.bf16.bf16.f32 "
                    "{%0,%1,%2,%3}, {%4,%5,%6,%7}, {%8,%9}, {%0,%1,%2,%3};"
                    : "+f"(c1[0]), "+f"(c1[1]), "+f"(c1[2]), "+f"(c1[3])
                    : "r"(a[k][0]), "r"(a[k][1]), "r"(a[k][2]), "r"(a[k][3]),
                      "r"(b[k][2]), "r"(b[k][3]));
            }
            int colg = coltile + n0 + 2 * (lane & 3);
            float m0v = fmaxf(fmaxf(c0[0], c0[1]), fmaxf(c1[0], c1[1]));
            if (m0v > vmin0) {
                insU(c0[0], colg, tv[0], ti[0], vmin0);
                insU(c0[1], colg + 1, tv[0], ti[0], vmin0);
                insU(c1[0], colg + 8, tv[0], ti[0], vmin0);
                insU(c1[1], colg + 9, tv[0], ti[0], vmin0);
            }
            float m1v = fmaxf(fmaxf(c0[2], c0[3]), fmaxf(c1[2], c1[3]));
            if (m1v > vmin1) {
                insU(c0[2], colg, tv[1], ti[1], vmin1);
                insU(c0[3], colg + 1, tv[1], ti[1], vmin1);
                insU(c1[2], colg + 8, tv[1], ti[1], vmin1);
                insU(c1[3], colg + 9, tv[1], ti[1], vmin1);
            }
        }
    }

    int slot = ch * 4 + (lane & 3);
    int rlo = row0 + m0 + (lane >> 2);
#pragma unroll
    for (int h = 0; h < 2; h++) {
        int row = rlo + h * 8;
        size_t base = (size_t)row * 128 + split * 64 + slot * 4;
#pragma unroll
        for (int j = 0; j < 4; j++) {
            ull key = ((ull)ordf(tv[h][j]) << 32) | (uint32_t)(~ti[h][j]);
            g_cand2[base + j] = key;
        }
    }
}

// ---------------------------------------------------------------------------
// kS: warp per row. 128 approx keys -> approx top-16 -> exact rescore -> top-4.
// ---------------------------------------------------------------------------
__global__ __launch_bounds__(256) void kS()
{
    int tid = threadIdx.x, lane = tid & 31, wid = tid >> 5;
    int row = blockIdx.x * 8 + wid;

    ull key[4];
    {
        const ulonglong2* cp = (const ulonglong2*)&g_cand2[(size_t)row * 128];
        ulonglong2 ka = cp[lane * 2], kb = cp[lane * 2 + 1];
        key[0] = ka.x; key[1] = ka.y; key[2] = kb.x; key[3] = kb.y;
    }

    int myIdx = 0;
#pragma unroll
    for (int r = 0; r < 16; r++) {
        ull best = key[0];
#pragma unroll
        for (int j = 1; j < 4; j++) best = (key[j] > best) ? key[j] : best;
#pragma unroll
        for (int off = 16; off; off >>= 1) {
            ull o = __shfl_xor_sync(0xffffffff, best, off);
            if (o > best) best = o;
        }
        if (lane == r) myIdx = (int)(~(uint32_t)best);
#pragma unroll
        for (int j = 0; j < 4; j++)
            if (key[j] == best) key[j] = 0;
    }

    ull ek = 0;
    if (lane < 16) {
        const float4* qp = (const float4*)&g_q[(size_t)row * 64];
        const float4* kp = (const float4*)&g_k[(size_t)myIdx * 64];
        float acc = 0.f;
#pragma unroll
        for (int i = 0; i < 16; i++) {
            float4 qv = qp[i];
            float4 kv = kp[i];
            acc = fmaf(qv.x, kv.x, acc);
            acc = fmaf(qv.y, kv.y, acc);
            acc = fmaf(qv.z, kv.z, acc);
            acc = fmaf(qv.w, kv.w, acc);
        }
        ek = ((ull)ordf(acc) << 32) | (uint32_t)(~myIdx);
    }
#pragma unroll
    for (int r4 = 0; r4 < 4; r4++) {
        ull best = ek;
#pragma unroll
        for (int off = 16; off; off >>= 1) {
            ull o = __shfl_xor_sync(0xffffffff, best, off);
            if (o > best) best = o;
        }
        if (lane == 0) g_ctx[row * 4 + r4] = (int)(~(uint32_t)best);
        if (ek == best) ek = 0;
    }
}

// ---------------------------------------------------------------------------
// kP: precompute rule-combined time-conv matrices C[r][24][36] and the
// per-rule noise weight sums g_NZ[r][32].
// ---------------------------------------------------------------------------
__global__ void kP(
    const float* __restrict__ w_indiv, const float* __restrict__ w_social,
    const float* __restrict__ tp_w, const float* __restrict__ tp_b,
    const float* __restrict__ tpr_w, const float* __restrict__ tpr_b,
    const float* __restrict__ tpi_w, const float* __restrict__ tpi_b,
    const float* __restrict__ tpir_w, const float* __restrict__ tpir_b,
    const float* __restrict__ sp_w, const float* __restrict__ spr_w,
    const float* __restrict__ spi_w, const float* __restrict__ spir_w)
{
    int t = threadIdx.x;
    if (t < 192) {
        int r = t / 24, o2 = t % 24, o = o2 >> 1, pos = o2 & 1;
        float wi = w_indiv[r], ws = w_social[r];
        float* dst = g_C + (r * 24 + o2) * 36;
#pragma unroll
        for (int c = 0; c < 8; c++) {
            int wb = (r * 12 + o) * 8 + c;
            const float* wt = tpi_w + wb * 3;
            float wri = tpir_w[wb];
            float ci0 = pos == 0 ? (wt[1] + wri) : wt[0];
            float ci1 = pos == 0 ? wt[2] : (wt[1] + wri);
            dst[c] = wi * ci0;
            dst[8 + c] = wi * ci1;
            const float* ut = tp_w + wb * 3;
            float urs = tpr_w[wb];
            float cs0 = pos == 0 ? (ut[1] + urs) : ut[0];
            float cs1 = pos == 0 ? ut[2] : (ut[1] + urs);
            dst[16 + c] = ws * cs0;
            dst[24 + c] = ws * cs1;
        }
        dst[32] = wi * (tpi_b[r * 12 + o] + tpir_b[r * 12 + o])
                + ws * (tp_b[r * 12 + o] + tpr_b[r * 12 + o]);
        dst[33] = 0.f; dst[34] = 0.f; dst[35] = 0.f;
    } else if (t < 256) {
        int item = t - 192;
        int r = item >> 3, sub = item & 7;
        int path = sub >> 2, so = (sub >> 1) & 1, p = sub & 1;
        float Wall = 0.f, Wf = 0.f, Wl = 0.f, W1 = 0.f;
        if (path == 0) {
            const float* w3 = spi_w + r * 12 + so * 6 + p * 3;
            Wall = w3[0] + w3[1] + w3[2]; Wf = w3[0]; Wl = w3[2];
            W1 = spir_w[r * 4 + so * 2 + p];
        } else {
            for (int ci = p; ci < 10; ci += 2) {
                const float* w3 = sp_w + r * 60 + so * 30 + ci * 3;
                Wall += w3[0] + w3[1] + w3[2]; Wf += w3[0]; Wl += w3[2];
                W1 += spr_w[r * 20 + so * 10 + ci];
            }
        }
        float* dst = g_NZ + r * 32 + path * 16;
        dst[0 + so * 2 + p] = Wall;
        dst[4 + so * 2 + p] = Wf;
        dst[8 + so * 2 + p] = Wl;
        dst[12 + so * 2 + p] = W1;
    }
}

// ---------------------------------------------------------------------------
// kC: phase1 per-node noise-free convs (shared), phase2 per-(n,b) noise-add
// + combined matvec. 8 nodes x 20 b per block.
// ---------------------------------------------------------------------------
__global__ __launch_bounds__(160) void kC(
    const float* __restrict__ obs_vel, const float* __restrict__ noise,
    const float* __restrict__ w_noise,
    const float* __restrict__ sp_w, const float* __restrict__ sp_b,
    const float* __restrict__ spr_w, const float* __restrict__ spr_b,
    const float* __restrict__ spi_w, const float* __restrict__ spi_b,
    const float* __restrict__ spir_w, const float* __restrict__ spir_b,
    float* __restrict__ out)
{
    __shared__ __align__(16) float s_C[8 * 24 * 36];
    __shared__ float s_sp_w[480], s_sp_b[16], s_spr_w[160], s_spr_b[16];
    __shared__ float s_spi_w[96], s_spi_b[16], s_spir_w[32], s_spir_b[16];
    __shared__ float s_NZ[8 * 32];
    __shared__ float s_wn[8], s_noise[BB * 2];
    __shared__ float s_ov[128], s_cvx[512];
    __shared__ int s_rule[8];
    __shared__ float sP[8][4][8], sQ[8][4][8];

    int tid = threadIdx.x;
    int n0 = blockIdx.x * 8;

    for (int i = tid; i < 8 * 24 * 36; i += 160) s_C[i] = g_C[i];
    for (int i = tid; i < 480; i += 160) s_sp_w[i] = sp_w[i];
    for (int i = tid; i < 256; i += 160) s_NZ[i] = g_NZ[i];
    if (tid < 160) s_spr_w[tid] = spr_w[tid];
    if (tid < 96) s_spi_w[tid] = spi_w[tid];
    if (tid < 32) s_spir_w[tid] = spir_w[tid];
    if (tid < 16) {
        s_sp_b[tid] = sp_b[tid]; s_spr_b[tid] = spr_b[tid];
        s_spi_b[tid] = spi_b[tid]; s_spir_b[tid] = spir_b[tid];
    }
    if (tid < 8) { s_wn[tid] = w_noise[tid]; s_rule[tid] = g_rule[n0 + tid]; }
    if (tid < 40) s_noise[tid] = noise[tid];
    for (int i = tid; i < 128; i += 160) {
        int node = i >> 4, s = (i >> 3) & 1, t = i & 7;
        s_ov[i] = obs_vel[s * NN * TT + (n0 + node) * TT + t];
    }
    for (int i = tid; i < 512; i += 160) {
        int node = i >> 6, rem = i & 63, k = rem >> 4, s = (rem >> 3) & 1, t = rem & 7;
        int nb = g_ctx[(n0 + node) * 4 + k];
        s_cvx[i] = obs_vel[s * NN * TT + nb * TT + t];
    }
    __syncthreads();

    // phase 1: 256 items = node(8) x g(4: si0,si1,ss0,ss1) x t(8)
    for (int it = tid; it < 256; it += 160) {
        int node = it >> 5, g = (it >> 3) & 3, t = it & 7;
        int so = g & 1;
        int r = s_rule[node];
        const float* ov = s_ov + node * 16;
        const float* cv = s_cvx + node * 64;
        float a, q;
        if (g < 2) {
            const float* w3 = s_spi_w + r * 12 + so * 6;
            const float* w1 = s_spir_w + r * 4 + so * 2;
            a = s_spi_b[r * 2 + so];
            q = s_spir_b[r * 2 + so];
#pragma unroll
            for (int ci = 0; ci < 2; ci++) {
                const float* x = ov + ci * 8;
                a = fmaf(w3[ci * 3 + 1], x[t], a);
                if (t > 0) a = fmaf(w3[ci * 3 + 0], x[t - 1], a);
                if (t < 7) a = fmaf(w3[ci * 3 + 2], x[t + 1], a);
                q = fmaf(w1[ci], x[t], q);
            }
        } else {
            const float* w3 = s_sp_w + r * 60 + so * 30;
            const float* w1 = s_spr_w + r * 20 + so * 10;
            a = s_sp_b[r * 2 + so];
            q = s_spr_b[r * 2 + so];
#pragma unroll
            for (int ci = 0; ci < 10; ci++) {
                const float* x = (ci < 2) ? (ov + ci * 8) : (cv + (ci - 2) * 8);
                a = fmaf(w3[ci * 3 + 1], x[t], a);
                if (t > 0) a = fmaf(w3[ci * 3 + 0], x[t - 1], a);
                if (t < 7) a = fmaf(w3[ci * 3 + 2], x[t + 1], a);
                q = fmaf(w1[ci], x[t], q);
            }
        }
        sP[node][g][t] = a;
        sQ[node][g][t] = q;
    }
    __syncthreads();

    // phase 2
    int node = tid / 20, b = tid - node * 20;
    int n = n0 + node;
    int r = s_rule[node];
    float wn = s_wn[r];
    float nz0 = s_noise[b * 2 + 0] * wn;
    float nz1 = s_noise[b * 2 + 1] * wn;

    float vals[32];
    const float* NZ = s_NZ + r * 32;
#pragma unroll
    for (int path = 0; path < 2; path++) {
        const float* Z = NZ + path * 16;
#pragma unroll
        for (int so = 0; so < 2; so++) {
            float nzm = Z[0 + so * 2] * nz0 + Z[1 + so * 2] * nz1;
            float nzf = Z[4 + so * 2] * nz0 + Z[5 + so * 2] * nz1;
            float nzl = Z[8 + so * 2] * nz0 + Z[9 + so * 2] * nz1;
            float nzq = Z[12 + so * 2] * nz0 + Z[13 + so * 2] * nz1;
            int g = path * 2 + so;
#pragma unroll
            for (int t = 0; t < 8; t++) {
                float addn = nzm;
                if (t == 0) addn -= nzf;
                if (t == 7) addn -= nzl;
                float pre = sP[node][g][t] + addn;
                vals[path * 16 + so * 8 + t] = fmaxf(pre, 0.f) + sQ[node][g][t] + nzq;
            }
        }
    }

    ull pk[16];
#pragma unroll
    for (int p = 0; p < 16; p++) pk[p] = pack2(vals[2 * p], vals[2 * p + 1]);

    const float* Cb = s_C + r * 24 * 36;
    float* outp = out + ((size_t)b * NN + n) * 24;
#pragma unroll 4
    for (int o2 = 0; o2 < 24; o2++) {
        const ulonglong2* cp = (const ulonglong2*)(Cb + o2 * 36);
        ull acc = pack2(Cb[o2 * 36 + 32], 0.f);
#pragma unroll
        for (int p = 0; p < 8; p++) {
            ulonglong2 cc = cp[p];
            acc = fma2(cc.x, pk[2 * p], acc);
            acc = fma2(cc.y, pk[2 * p + 1], acc);
        }
        float lo, hi;
        unpack2(acc, lo, hi);
        outp[o2] = lo + hi;
    }
}

// ---------------------------------------------------------------------------
extern "C" void kernel_launch(void* const* d_in, const int* in_sizes, int n_in,
                              void* d_out, int out_size)
{
    const float* obs      = (const float*)d_in[0];
    const float* obs_vel  = (const float*)d_in[1];
    const float* noise    = (const float*)d_in[2];
    const float* wq_rule  = (const float*)d_in[3];
    const float* bq_rule  = (const float*)d_in[4];
    const float* wq_ctx   = (const float*)d_in[5];
    const float* bq_ctx   = (const float*)d_in[6];
    const float* wk_ctx   = (const float*)d_in[7];
    const float* bk_ctx   = (const float*)d_in[8];
    const float* rule_emb = (const float*)d_in[9];
    const float* w_noise  = (const float*)d_in[10];
    const float* w_indiv  = (const float*)d_in[11];
    const float* w_social = (const float*)d_in[12];
    const float* sp_w  = (const float*)d_in[13];
    const float* sp_b  = (const float*)d_in[14];
    const float* spr_w = (const float*)d_in[15];
    const float* spr_b = (const float*)d_in[16];
    const float* tp_w  = (const float*)d_in[17];
    const float* tp_b  = (const float*)d_in[18];
    const float* tpr_w = (const float*)d_in[19];
    const float* tpr_b = (const float*)d_in[20];
    const float* spi_w  = (const float*)d_in[21];
    const float* spi_b  = (const float*)d_in[22];
    const float* spir_w = (const float*)d_in[23];
    const float* spir_b = (const float*)d_in[24];
    const float* tpi_w  = (const float*)d_in[25];
    const float* tpi_b  = (const float*)d_in[26];
    const float* tpir_w = (const float*)d_in[27];
    const float* tpir_b = (const float*)d_in[28];
    float* out = (float*)d_out;

    static bool attr_set = false;
    if (!attr_set) {
        cudaFuncSetAttribute(kB_hmma, cudaFuncAttributeMaxDynamicSharedMemorySize, 69632);
        attr_set = true;
    }

    kA<<<128, 256>>>(obs, obs_vel, wq_rule, bq_rule, wq_ctx, bq_ctx, wk_ctx, bk_ctx,
                     rule_emb);
    kP<<<1, 256>>>(w_indiv, w_social, tp_w, tp_b, tpr_w, tpr_b,
                   tpi_w, tpi_b, tpir_w, tpir_b,
                   sp_w, spr_w, spi_w, spir_w);
    kB_hmma<<<dim3(128, 2), 256, 69632>>>();
    kS<<<512, 256>>>();
    kC<<<512, 160>>>(obs_vel, noise, w_noise,
                     sp_w, sp_b, spr_w, spr_b,
                     spi_w, spi_b, spir_w, spir_b, out);
}

// round 14
// speedup vs baseline: 1.8119x; 1.1017x over previous
#include <cuda_runtime.h>
#include <cuda_bf16.h>
#include <cstdint>

#define NN 4096
#define TT 8
#define KTOP 4
#define RR 8
#define DKK 64
#define BB 20

typedef unsigned long long ull;

__device__ __align__(16) float g_q[NN * DKK];
__device__ __align__(16) float g_k[NN * DKK];
__device__ __align__(16) __nv_bfloat16 g_qh[NN * DKK];
__device__ __align__(16) __nv_bfloat16 g_kh[NN * DKK];
__device__ __align__(16) float g_C[RR * 24 * 36];
__device__ __align__(16) float g_NZ[RR * 32];
__device__ __align__(16) ull g_cand2[NN * 128];
__device__ int g_ctx[NN * KTOP];
__device__ int g_rule[NN];

// ---------------- small helpers ----------------
__device__ __forceinline__ ull pack2(float a, float b) {
    ull r;
    asm("mov.b64 %0, {%1, %2};" : "=l"(r) : "f"(a), "f"(b));
    return r;
}
__device__ __forceinline__ void unpack2(ull v, float& a, float& b) {
    asm("mov.b64 {%0, %1}, %2;" : "=f"(a), "=f"(b) : "l"(v));
}
__device__ __forceinline__ ull fma2(ull a, ull b, ull c) {
    ull d;
    asm("fma.rn.f32x2 %0, %1, %2, %3;" : "=l"(d) : "l"(a), "l"(b), "l"(c));
    return d;
}
__device__ __forceinline__ void insU(float v, int c, float* tv, int* ti, float& vmin) {
    if (v > vmin) {
        bool done = false;
#pragma unroll
        for (int j = 0; j < 4; j++) {
            if (!done && tv[j] == vmin) { tv[j] = v; ti[j] = c; done = true; }
        }
        vmin = fminf(fminf(tv[0], tv[1]), fminf(tv[2], tv[3]));
    }
}
__device__ __forceinline__ uint32_t ordf(float v) {
    uint32_t u = __float_as_uint(v);
    return (u & 0x80000000u) ? ~u : (u | 0x80000000u);
}
__device__ __forceinline__ uint32_t smem_to_u32(const void* p) {
    uint32_t a;
    asm("{ .reg .u64 t; cvta.to.shared.u64 t, %1; cvt.u32.u64 %0, t; }" : "=r"(a) : "l"(p));
    return a;
}
#define SWZ(row, byteoff) \
    ((row) * 128 + (((((byteoff) >> 4) ^ ((row) & 7)) << 4)) + ((byteoff) & 15))

// ---------------------------------------------------------------------------
// kA: x[4096x32] @ W[32x192] -> g_q | g_k | rq(smem), + fused rule argmax.
// ---------------------------------------------------------------------------
__global__ __launch_bounds__(256) void kA(
    const float* __restrict__ obs, const float* __restrict__ obs_vel,
    const float* __restrict__ wq_rule, const float* __restrict__ bq_rule,
    const float* __restrict__ wq_ctx, const float* __restrict__ bq_ctx,
    const float* __restrict__ wk_ctx, const float* __restrict__ bk_ctx,
    const float* __restrict__ rule_emb)
{
    __shared__ __align__(16) ull x2_s[32 * 32];
    __shared__ __align__(16) ull w_s[32 * 96];
    __shared__ float s_rqv[32 * 64];
    __shared__ float s_lg[32 * 8];
    __shared__ float s_emb[64 * 8];
    int tid = threadIdx.x;
    int n0 = blockIdx.x * 32;

    float* xf = (float*)x2_s;
    for (int e = tid; e < 32 * 32; e += 256) {
        int i = e >> 5, node = e & 31;
        int t = i >> 2, c = i & 3;
        const float* src = (c < 2) ? obs : obs_vel;
        float v = src[(c & 1) * NN * TT + (n0 + node) * TT + t];
        xf[e * 2] = v; xf[e * 2 + 1] = v;
    }
    float* wf = (float*)w_s;
    for (int e = tid; e < 32 * 192; e += 256) {
        int i = e / 192, col = e % 192;
        float v;
        if (col < 64) v = wq_ctx[i * 64 + col];
        else if (col < 128) v = wk_ctx[i * 64 + col - 64];
        else {
            int c = i & 3;
            if (c >= 2) v = wq_rule[((i >> 2) * 2 + (c - 2)) * 64 + (col - 128)];
            else v = 0.f;
        }
        wf[i * 192 + col] = v;
    }
    for (int e = tid; e < 512; e += 256) s_emb[e] = rule_emb[(e & 7) * 64 + (e >> 3)];
    __syncthreads();

    int w = tid >> 5, tx = tid & 31;
    int rbase = w * 4;
    ull bp[3];
#pragma unroll
    for (int j = 0; j < 3; j++) {
        int c2 = (tx * 3 + j) * 2;
        float b0, b1;
        if (c2 < 64) { b0 = bq_ctx[c2]; b1 = bq_ctx[c2 + 1]; }
        else if (c2 < 128) { b0 = bk_ctx[c2 - 64]; b1 = bk_ctx[c2 - 63]; }
        else { b0 = bq_rule[c2 - 128]; b1 = bq_rule[c2 - 127]; }
        bp[j] = pack2(b0, b1);
    }
    ull acc[4][3];
#pragma unroll
    for (int r = 0; r < 4; r++)
#pragma unroll
        for (int j = 0; j < 3; j++) acc[r][j] = bp[j];

#pragma unroll 8
    for (int kk = 0; kk < 32; kk++) {
        const ulonglong2* qp = (const ulonglong2*)(x2_s + kk * 32 + rbase);
        ulonglong2 q0 = qp[0], q1 = qp[1];
        ull qr[4] = { q0.x, q0.y, q1.x, q1.y };
        ull wv0 = w_s[kk * 96 + tx * 3 + 0];
        ull wv1 = w_s[kk * 96 + tx * 3 + 1];
        ull wv2 = w_s[kk * 96 + tx * 3 + 2];
#pragma unroll
        for (int r = 0; r < 4; r++) {
            acc[r][0] = fma2(qr[r], wv0, acc[r][0]);
            acc[r][1] = fma2(qr[r], wv1, acc[r][1]);
            acc[r][2] = fma2(qr[r], wv2, acc[r][2]);
        }
    }
#pragma unroll
    for (int r = 0; r < 4; r++) {
        int nodeL = rbase + r;
        int node = n0 + nodeL;
#pragma unroll
        for (int j = 0; j < 3; j++) {
            int c2 = (tx * 3 + j) * 2;
            float v0, v1;
            unpack2(acc[r][j], v0, v1);
            int cc = c2 & 63;
            if (c2 < 64) {
                g_q[node * 64 + cc] = v0;
                g_q[node * 64 + cc + 1] = v1;
                *(__nv_bfloat162*)&g_qh[node * 64 + cc] = __floats2bfloat162_rn(v0, v1);
            } else if (c2 < 128) {
                g_k[node * 64 + cc] = v0;
                g_k[node * 64 + cc + 1] = v1;
                *(__nv_bfloat162*)&g_kh[node * 64 + cc] = __floats2bfloat162_rn(v0, v1);
            } else {
                s_rqv[nodeL * 64 + cc] = v0;
                s_rqv[nodeL * 64 + cc + 1] = v1;
            }
        }
    }
    __syncthreads();
    {
        int node = tid >> 3, rr = tid & 7;
        float a = 0.f;
        const float* rv = s_rqv + node * 64;
#pragma unroll 8
        for (int o = 0; o < 64; o++) a = fmaf(rv[o], s_emb[o * 8 + rr], a);
        s_lg[node * 8 + rr] = a;
    }
    __syncthreads();
    if (tid < 32) {
        const float* lg = s_lg + tid * 8;
        int best = 0;
        float bv = lg[0];
#pragma unroll
        for (int r = 1; r < 8; r++)
            if (lg[r] > bv) { bv = lg[r]; best = r; }
        g_rule[n0 + tid] = best;
    }
}

// ---------------------------------------------------------------------------
// kB_hmma: bf16 HMMA scores + per-thread keep-4 candidates (u64 keys).
// grid (128 rowblocks, 2 colsplits) x 256 thr. Hoisted LDSM offsets.
// ---------------------------------------------------------------------------
__global__ __launch_bounds__(256, 3) void kB_hmma()
{
    extern __shared__ char smem[];
    char* As = smem;               // 32 x 128B
    char* Bs0 = smem + 4096;       // 256 x 128B
    char* Bs1 = smem + 4096 + 32768;
    int tid = threadIdx.x, lane = tid & 31, wid = tid >> 5;
    int row0 = blockIdx.x * 32;
    int split = blockIdx.y;
    int colbase = split * 2048;

    {
        int r = tid >> 3, c = tid & 7;
        uint4 v = *(const uint4*)((const char*)g_qh + (size_t)(row0 + r) * 128 + c * 16);
        *(uint4*)(As + r * 128 + ((c ^ (r & 7)) << 4)) = v;
    }
    {
        int r = tid;
        const char* src = (const char*)g_kh + (size_t)(colbase + r) * 128;
        char* dst = Bs0 + r * 128;
#pragma unroll
        for (int c = 0; c < 8; c++) {
            uint32_t daddr = smem_to_u32(dst + ((c ^ (r & 7)) << 4));
            asm volatile("cp.async.cg.shared.global [%0], [%1], 16;"
                         :: "r"(daddr), "l"(src + c * 16));
        }
        asm volatile("cp.async.commit_group;");
    }
    __syncthreads();

    int rg = wid >> 2, ch = wid & 3;
    int m0 = rg * 16;

    uint32_t a[4][4];
    {
        int arow = m0 + (lane & 15);
        int kbh = ((lane >> 4) & 1) * 16;
#pragma unroll
        for (int k = 0; k < 4; k++) {
            int byteoff = k * 32 + kbh;
            uint32_t addr = smem_to_u32(As + SWZ(arow, byteoff));
            asm volatile("ldmatrix.sync.aligned.m8n8.x4.shared.b16 {%0,%1,%2,%3}, [%4];"
                : "=r"(a[k][0]), "=r"(a[k][1]), "=r"(a[k][2]), "=r"(a[k][3]) : "r"(addr));
        }
    }

    // hoist per-thread B-fragment swizzled offsets: boff[np][k]
    uint32_t b0base = smem_to_u32(Bs0);
    uint32_t bXOR = b0base ^ smem_to_u32(Bs1);
    uint32_t boff[4][4];
    {
        int brow_off = (lane & 7) + ((lane & 16) >> 1);
        int bkb = (lane & 8) ? 16 : 0;
#pragma unroll
        for (int np = 0; np < 4; np++) {
            int brow = ch * 64 + np * 16 + brow_off;
#pragma unroll
            for (int k = 0; k < 4; k++)
                boff[np][k] = SWZ(brow, k * 32 + bkb);
        }
    }

    float tv[2][4];
    int ti[2][4];
    float vmin0 = -3.4e38f, vmin1 = -3.4e38f;
#pragma unroll
    for (int h = 0; h < 2; h++)
#pragma unroll
        for (int j = 0; j < 4; j++) { tv[h][j] = -3.4e38f; ti[h][j] = 0; }

    uint32_t Bcur = b0base;
#pragma unroll
    for (int t = 0; t < 8; t++) {
        asm volatile("cp.async.wait_group 0;");
        __syncthreads();
        if (t < 7) {
            char* dst0 = ((t + 1) & 1) ? Bs1 : Bs0;
            int r = tid;
            const char* src = (const char*)g_kh + (size_t)(colbase + (t + 1) * 256 + r) * 128;
            char* dst = dst0 + r * 128;
#pragma unroll
            for (int c = 0; c < 8; c++) {
                uint32_t daddr = smem_to_u32(dst + ((c ^ (r & 7)) << 4));
                asm volatile("cp.async.cg.shared.global [%0], [%1], 16;"
                             :: "r"(daddr), "l"(src + c * 16));
            }
            asm volatile("cp.async.commit_group;");
        }

        int coltile = colbase + t * 256;
#pragma unroll
        for (int np = 0; np < 4; np++) {
            int n0 = ch * 64 + np * 16;
            uint32_t b[4][4];
#pragma unroll
            for (int k = 0; k < 4; k++) {
                asm volatile("ldmatrix.sync.aligned.m8n8.x4.shared.b16 {%0,%1,%2,%3}, [%4];"
                    : "=r"(b[k][0]), "=r"(b[k][1]), "=r"(b[k][2]), "=r"(b[k][3])
                    : "r"(Bcur + boff[np][k]));
            }
            float c0[4] = {0.f, 0.f, 0.f, 0.f};
            float c1[4] = {0.f, 0.f, 0.f, 0.f};
#pragma unroll
            for (int k = 0; k < 4; k++) {
                asm volatile(
                    "mma.sync.aligned.m16n8k16.row.col.f32.bf16.bf16.f32 "
                    "{%0,%1,%2,%3}, {%4,%5,%6,%7}, {%8,%9}, {%0,%1,%2,%3};"
                    : "+f"(c0[0]), "+f"(c0[1]), "+f"(c0[2]), "+f"(c0[3])
                    : "r"(a[k][0]), "r"(a[k][1]), "r"(a[k][2]), "r"(a[k][3]),
                      "r"(b[k][0]), "r"(b[k][1]));
                asm volatile(
                    "mma.sync.aligned.m16n8k16.row.col.f32.bf16.bf16.f32 "
                    "{%0,%1,%2,%3}, {%4,%5,%6,%7}, {%8,%9}, {%0,%1,%2,%3};"
                    : "+f"(c1[0]), "+f"(c1[1]), "+f"(c1[2]), "+f"(c1[3])
                    : "r"(a[k][0]), "r"(a[k][1]), "r"(a[k][2]), "r"(a[k][3]),
                      "r"(b[k][2]), "r"(b[k][3]));
            }
            int colg = coltile + n0 + 2 * (lane & 3);
            float m0v = fmaxf(fmaxf(c0[0], c0[1]), fmaxf(c1[0], c1[1]));
            if (m0v > vmin0) {
                insU(c0[0], colg, tv[0], ti[0], vmin0);
                insU(c0[1], colg + 1, tv[0], ti[0], vmin0);
                insU(c1[0], colg + 8, tv[0], ti[0], vmin0);
                insU(c1[1], colg + 9, tv[0], ti[0], vmin0);
            }
            float m1v = fmaxf(fmaxf(c0[2], c0[3]), fmaxf(c1[2], c1[3]));
            if (m1v > vmin1) {
                insU(c0[2], colg, tv[1], ti[1], vmin1);
                insU(c0[3], colg + 1, tv[1], ti[1], vmin1);
                insU(c1[2], colg + 8, tv[1], ti[1], vmin1);
                insU(c1[3], colg + 9, tv[1], ti[1], vmin1);
            }
        }
        Bcur ^= bXOR;
    }

    int slot = ch * 4 + (lane & 3);
    int rlo = row0 + m0 + (lane >> 2);
#pragma unroll
    for (int h = 0; h < 2; h++) {
        int row = rlo + h * 8;
        size_t base = (size_t)row * 128 + split * 64 + slot * 4;
#pragma unroll
        for (int j = 0; j < 4; j++) {
            ull key = ((ull)ordf(tv[h][j]) << 32) | (uint32_t)(~ti[h][j]);
            g_cand2[base + j] = key;
        }
    }
}

// ---------------------------------------------------------------------------
// kS: warp per row. 128 approx keys -> approx top-8 -> exact rescore -> top-4.
// ---------------------------------------------------------------------------
__global__ __launch_bounds__(256) void kS()
{
    int tid = threadIdx.x, lane = tid & 31, wid = tid >> 5;
    int row = blockIdx.x * 8 + wid;

    ull key[4];
    {
        const ulonglong2* cp = (const ulonglong2*)&g_cand2[(size_t)row * 128];
        ulonglong2 ka = cp[lane * 2], kb = cp[lane * 2 + 1];
        key[0] = ka.x; key[1] = ka.y; key[2] = kb.x; key[3] = kb.y;
    }

    int myIdx = 0;
#pragma unroll
    for (int r = 0; r < 8; r++) {
        ull best = key[0];
#pragma unroll
        for (int j = 1; j < 4; j++) best = (key[j] > best) ? key[j] : best;
#pragma unroll
        for (int off = 16; off; off >>= 1) {
            ull o = __shfl_xor_sync(0xffffffff, best, off);
            if (o > best) best = o;
        }
        if (lane == r) myIdx = (int)(~(uint32_t)best);
#pragma unroll
        for (int j = 0; j < 4; j++)
            if (key[j] == best) key[j] = 0;
    }

    ull ek = 0;
    if (lane < 8) {
        const float4* qp = (const float4*)&g_q[(size_t)row * 64];
        const float4* kp = (const float4*)&g_k[(size_t)myIdx * 64];
        float acc = 0.f;
#pragma unroll
        for (int i = 0; i < 16; i++) {
            float4 qv = qp[i];
            float4 kv = kp[i];
            acc = fmaf(qv.x, kv.x, acc);
            acc = fmaf(qv.y, kv.y, acc);
            acc = fmaf(qv.z, kv.z, acc);
            acc = fmaf(qv.w, kv.w, acc);
        }
        ek = ((ull)ordf(acc) << 32) | (uint32_t)(~myIdx);
    }
#pragma unroll
    for (int r4 = 0; r4 < 4; r4++) {
        ull best = ek;
#pragma unroll
        for (int off = 4; off; off >>= 1) {
            ull o = __shfl_xor_sync(0xffffffff, best, off);
            if (o > best) best = o;
        }
        best = __shfl_sync(0xffffffff, best, 0);
        if (lane == 0) g_ctx[row * 4 + r4] = (int)(~(uint32_t)best);
        if (ek == best) ek = 0;
    }
}

// ---------------------------------------------------------------------------
// kP: precompute rule-combined time-conv matrices C[r][24][36] and g_NZ.
// ---------------------------------------------------------------------------
__global__ void kP(
    const float* __restrict__ w_indiv, const float* __restrict__ w_social,
    const float* __restrict__ tp_w, const float* __restrict__ tp_b,
    const float* __restrict__ tpr_w, const float* __restrict__ tpr_b,
    const float* __restrict__ tpi_w, const float* __restrict__ tpi_b,
    const float* __restrict__ tpir_w, const float* __restrict__ tpir_b,
    const float* __restrict__ sp_w, const float* __restrict__ spr_w,
    const float* __restrict__ spi_w, const float* __restrict__ spir_w)
{
    int t = threadIdx.x;
    if (t < 192) {
        int r = t / 24, o2 = t % 24, o = o2 >> 1, pos = o2 & 1;
        float wi = w_indiv[r], ws = w_social[r];
        float* dst = g_C + (r * 24 + o2) * 36;
#pragma unroll
        for (int c = 0; c < 8; c++) {
            int wb = (r * 12 + o) * 8 + c;
            const float* wt = tpi_w + wb * 3;
            float wri = tpir_w[wb];
            float ci0 = pos == 0 ? (wt[1] + wri) : wt[0];
            float ci1 = pos == 0 ? wt[2] : (wt[1] + wri);
            dst[c] = wi * ci0;
            dst[8 + c] = wi * ci1;
            const float* ut = tp_w + wb * 3;
            float urs = tpr_w[wb];
            float cs0 = pos == 0 ? (ut[1] + urs) : ut[0];
            float cs1 = pos == 0 ? ut[2] : (ut[1] + urs);
            dst[16 + c] = ws * cs0;
            dst[24 + c] = ws * cs1;
        }
        dst[32] = wi * (tpi_b[r * 12 + o] + tpir_b[r * 12 + o])
                + ws * (tp_b[r * 12 + o] + tpr_b[r * 12 + o]);
        dst[33] = 0.f; dst[34] = 0.f; dst[35] = 0.f;
    } else if (t < 256) {
        int item = t - 192;
        int r = item >> 3, sub = item & 7;
        int path = sub >> 2, so = (sub >> 1) & 1, p = sub & 1;
        float Wall = 0.f, Wf = 0.f, Wl = 0.f, W1 = 0.f;
        if (path == 0) {
            const float* w3 = spi_w + r * 12 + so * 6 + p * 3;
            Wall = w3[0] + w3[1] + w3[2]; Wf = w3[0]; Wl = w3[2];
            W1 = spir_w[r * 4 + so * 2 + p];
        } else {
            for (int ci = p; ci < 10; ci += 2) {
                const float* w3 = sp_w + r * 60 + so * 30 + ci * 3;
                Wall += w3[0] + w3[1] + w3[2]; Wf += w3[0]; Wl += w3[2];
                W1 += spr_w[r * 20 + so * 10 + ci];
            }
        }
        float* dst = g_NZ + r * 32 + path * 16;
        dst[0 + so * 2 + p] = Wall;
        dst[4 + so * 2 + p] = Wf;
        dst[8 + so * 2 + p] = Wl;
        dst[12 + so * 2 + p] = W1;
    }
}

// ---------------------------------------------------------------------------
// kC: phase1 per-node noise-free convs (shared), phase2 per-(n,b) noise-add
// + combined matvec. 16 nodes x 20 b per block (320 thr), grid 256.
// ---------------------------------------------------------------------------
__global__ __launch_bounds__(320) void kC(
    const float* __restrict__ obs_vel, const float* __restrict__ noise,
    const float* __restrict__ w_noise,
    const float* __restrict__ sp_w, const float* __restrict__ sp_b,
    const float* __restrict__ spr_w, const float* __restrict__ spr_b,
    const float* __restrict__ spi_w, const float* __restrict__ spi_b,
    const float* __restrict__ spir_w, const float* __restrict__ spir_b,
    float* __restrict__ out)
{
    __shared__ __align__(16) float s_C[8 * 24 * 36];
    __shared__ float s_sp_w[480], s_sp_b[16], s_spr_w[160], s_spr_b[16];
    __shared__ float s_spi_w[96], s_spi_b[16], s_spir_w[32], s_spir_b[16];
    __shared__ float s_NZ[8 * 32];
    __shared__ float s_wn[8], s_noise[BB * 2];
    __shared__ float s_ov[256], s_cvx[1024];
    __shared__ int s_rule[16];
    __shared__ float sP[16][4][8], sQ[16][4][8];

    int tid = threadIdx.x;
    int n0 = blockIdx.x * 16;

    for (int i = tid; i < 8 * 24 * 36; i += 320) s_C[i] = g_C[i];
    for (int i = tid; i < 480; i += 320) s_sp_w[i] = sp_w[i];
    if (tid < 256) s_NZ[tid] = g_NZ[tid];
    if (tid < 160) s_spr_w[tid] = spr_w[tid];
    if (tid < 96) s_spi_w[tid] = spi_w[tid];
    if (tid < 32) s_spir_w[tid] = spir_w[tid];
    if (tid < 16) {
        s_sp_b[tid] = sp_b[tid]; s_spr_b[tid] = spr_b[tid];
        s_spi_b[tid] = spi_b[tid]; s_spir_b[tid] = spir_b[tid];
        s_rule[tid] = g_rule[n0 + tid];
    }
    if (tid < 8) s_wn[tid] = w_noise[tid];
    if (tid < 40) s_noise[tid] = noise[tid];
    for (int i = tid; i < 256; i += 320) {
        int node = i >> 4, s = (i >> 3) & 1, t = i & 7;
        s_ov[i] = obs_vel[s * NN * TT + (n0 + node) * TT + t];
    }
    for (int i = tid; i < 1024; i += 320) {
        int node = i >> 6, rem = i & 63, k = rem >> 4, s = (rem >> 3) & 1, t = rem & 7;
        int nb = g_ctx[(n0 + node) * 4 + k];
        s_cvx[i] = obs_vel[s * NN * TT + nb * TT + t];
    }
    __syncthreads();

    // phase 1: 512 items = node(16) x g(4) x t(8)
    for (int it = tid; it < 512; it += 320) {
        int node = it >> 5, g = (it >> 3) & 3, t = it & 7;
        int so = g & 1;
        int r = s_rule[node];
        const float* ov = s_ov + node * 16;
        const float* cv = s_cvx + node * 64;
        float a, q;
        if (g < 2) {
            const float* w3 = s_spi_w + r * 12 + so * 6;
            const float* w1 = s_spir_w + r * 4 + so * 2;
            a = s_spi_b[r * 2 + so];
            q = s_spir_b[r * 2 + so];
#pragma unroll
            for (int ci = 0; ci < 2; ci++) {
                const float* x = ov + ci * 8;
                a = fmaf(w3[ci * 3 + 1], x[t], a);
                if (t > 0) a = fmaf(w3[ci * 3 + 0], x[t - 1], a);
                if (t < 7) a = fmaf(w3[ci * 3 + 2], x[t + 1], a);
                q = fmaf(w1[ci], x[t], q);
            }
        } else {
            const float* w3 = s_sp_w + r * 60 + so * 30;
            const float* w1 = s_spr_w + r * 20 + so * 10;
            a = s_sp_b[r * 2 + so];
            q = s_spr_b[r * 2 + so];
#pragma unroll
            for (int ci = 0; ci < 10; ci++) {
                const float* x = (ci < 2) ? (ov + ci * 8) : (cv + (ci - 2) * 8);
                a = fmaf(w3[ci * 3 + 1], x[t], a);
                if (t > 0) a = fmaf(w3[ci * 3 + 0], x[t - 1], a);
                if (t < 7) a = fmaf(w3[ci * 3 + 2], x[t + 1], a);
                q = fmaf(w1[ci], x[t], q);
            }
        }
        sP[node][g][t] = a;
        sQ[node][g][t] = q;
    }
    __syncthreads();

    // phase 2
    int node = tid / 20, b = tid - node * 20;
    int n = n0 + node;
    int r = s_rule[node];
    float wn = s_wn[r];
    float nz0 = s_noise[b * 2 + 0] * wn;
    float nz1 = s_noise[b * 2 + 1] * wn;

    float vals[32];
    const float* NZ = s_NZ + r * 32;
#pragma unroll
    for (int path = 0; path < 2; path++) {
        const float* Z = NZ + path * 16;
#pragma unroll
        for (int so = 0; so < 2; so++) {
            float nzm = Z[0 + so * 2] * nz0 + Z[1 + so * 2] * nz1;
            float nzf = Z[4 + so * 2] * nz0 + Z[5 + so * 2] * nz1;
            float nzl = Z[8 + so * 2] * nz0 + Z[9 + so * 2] * nz1;
            float nzq = Z[12 + so * 2] * nz0 + Z[13 + so * 2] * nz1;
            int g = path * 2 + so;
#pragma unroll
            for (int t = 0; t < 8; t++) {
                float addn = nzm;
                if (t == 0) addn -= nzf;
                if (t == 7) addn -= nzl;
                float pre = sP[node][g][t] + addn;
                vals[path * 16 + so * 8 + t] = fmaxf(pre, 0.f) + sQ[node][g][t] + nzq;
            }
        }
    }

    ull pk[16];
#pragma unroll
    for (int p = 0; p < 16; p++) pk[p] = pack2(vals[2 * p], vals[2 * p + 1]);

    const float* Cb = s_C + r * 24 * 36;
    float* outp = out + ((size_t)b * NN + n) * 24;
#pragma unroll 4
    for (int o2 = 0; o2 < 24; o2++) {
        const ulonglong2* cp = (const ulonglong2*)(Cb + o2 * 36);
        ull acc = pack2(Cb[o2 * 36 + 32], 0.f);
#pragma unroll
        for (int p = 0; p < 8; p++) {
            ulonglong2 cc = cp[p];
            acc = fma2(cc.x, pk[2 * p], acc);
            acc = fma2(cc.y, pk[2 * p + 1], acc);
        }
        float lo, hi;
        unpack2(acc, lo, hi);
        outp[o2] = lo + hi;
    }
}

// ---------------------------------------------------------------------------
extern "C" void kernel_launch(void* const* d_in, const int* in_sizes, int n_in,
                              void* d_out, int out_size)
{
    const float* obs      = (const float*)d_in[0];
    const float* obs_vel  = (const float*)d_in[1];
    const float* noise    = (const float*)d_in[2];
    const float* wq_rule  = (const float*)d_in[3];
    const float* bq_rule  = (const float*)d_in[4];
    const float* wq_ctx   = (const float*)d_in[5];
    const float* bq_ctx   = (const float*)d_in[6];
    const float* wk_ctx   = (const float*)d_in[7];
    const float* bk_ctx   = (const float*)d_in[8];
    const float* rule_emb = (const float*)d_in[9];
    const float* w_noise  = (const float*)d_in[10];
    const float* w_indiv  = (const float*)d_in[11];
    const float* w_social = (const float*)d_in[12];
    const float* sp_w  = (const float*)d_in[13];
    const float* sp_b  = (const float*)d_in[14];
    const float* spr_w = (const float*)d_in[15];
    const float* spr_b = (const float*)d_in[16];
    const float* tp_w  = (const float*)d_in[17];
    const float* tp_b  = (const float*)d_in[18];
    const float* tpr_w = (const float*)d_in[19];
    const float* tpr_b = (const float*)d_in[20];
    const float* spi_w  = (const float*)d_in[21];
    const float* spi_b  = (const float*)d_in[22];
    const float* spir_w = (const float*)d_in[23];
    const float* spir_b = (const float*)d_in[24];
    const float* tpi_w  = (const float*)d_in[25];
    const float* tpi_b  = (const float*)d_in[26];
    const float* tpir_w = (const float*)d_in[27];
    const float* tpir_b = (const float*)d_in[28];
    float* out = (float*)d_out;

    static bool attr_set = false;
    if (!attr_set) {
        cudaFuncSetAttribute(kB_hmma, cudaFuncAttributeMaxDynamicSharedMemorySize, 69632);
        attr_set = true;
    }

    kA<<<128, 256>>>(obs, obs_vel, wq_rule, bq_rule, wq_ctx, bq_ctx, wk_ctx, bk_ctx,
                     rule_emb);
    kP<<<1, 256>>>(w_indiv, w_social, tp_w, tp_b, tpr_w, tpr_b,
                   tpi_w, tpi_b, tpir_w, tpir_b,
                   sp_w, spr_w, spi_w, spir_w);
    kB_hmma<<<dim3(128, 2), 256, 69632>>>();
    kS<<<512, 256>>>();
    kC<<<256, 320>>>(obs_vel, noise, w_noise,
                     sp_w, sp_b, spr_w, spr_b,
                     spi_w, spi_b, spir_w, spir_b, out);
}